// round 5
// baseline (speedup 1.0000x reference)
#include <cuda_runtime.h>

#define B_   8
#define S_   1024
#define D_   512
#define H_   8
#define DK_  64
#define DFF_ 2048
#define BS_  (B_ * S_)

// ---------------- scratch (no allocations allowed) ----------------
__device__ float g_q[BS_ * D_];
__device__ float g_k[BS_ * D_];
__device__ float g_v[BS_ * D_];
__device__ float g_attn[BS_ * D_];
__device__ float g_res[BS_ * D_];
__device__ float g_x1[BS_ * D_];
__device__ float g_x2[BS_ * D_];
__device__ float g_ff[BS_ * DFF_];
__device__ float g_stats[2 * B_];

// =================================================================
// Per-head projection GEMM:
//   C[n, h*64 + c] = sum_d A[n,d] * W[h, d, c] + bias[h, c]
// A: [M=8192, 512] row-major. W: [H, 512, 64]. C: [8192, 512].
// Grid: (M/64, 1, H). 256 threads, 64x64 tile, 4x4 per thread.
// =================================================================
__global__ __launch_bounds__(256) void gemm_head(
    const float* __restrict__ A, const float* __restrict__ W,
    const float* __restrict__ bias, float* __restrict__ C)
{
    const int h  = blockIdx.z;
    const int m0 = blockIdx.x * 64;
    __shared__ float As[16][68];
    __shared__ float Bs[16][64];

    const int tid = threadIdx.x;
    const int tx = tid & 15, ty = tid >> 4;
    float acc[4][4] = {};

    const float* Wh = W + (size_t)h * (D_ * 64);

    for (int kk = 0; kk < D_; kk += 16) {
        {   // A tile: row = tid>>2, 4 consecutive k
            int row = tid >> 2, k4 = (tid & 3) * 4;
            float4 a = *(const float4*)(A + (size_t)(m0 + row) * D_ + kk + k4);
            As[k4 + 0][row] = a.x; As[k4 + 1][row] = a.y;
            As[k4 + 2][row] = a.z; As[k4 + 3][row] = a.w;
        }
        {   // W tile: k = tid>>4, 4 consecutive n
            int k = tid >> 4, n4 = (tid & 15) * 4;
            *(float4*)&Bs[k][n4] = *(const float4*)(Wh + (size_t)(kk + k) * 64 + n4);
        }
        __syncthreads();
        #pragma unroll
        for (int k = 0; k < 16; k++) {
            float4 av = *(const float4*)&As[k][ty * 4];
            float4 bv = *(const float4*)&Bs[k][tx * 4];
            float a[4] = {av.x, av.y, av.z, av.w};
            float b[4] = {bv.x, bv.y, bv.z, bv.w};
            #pragma unroll
            for (int i = 0; i < 4; i++)
                #pragma unroll
                for (int j = 0; j < 4; j++)
                    acc[i][j] += a[i] * b[j];
        }
        __syncthreads();
    }
    #pragma unroll
    for (int i = 0; i < 4; i++) {
        int row = m0 + ty * 4 + i;
        #pragma unroll
        for (int j = 0; j < 4; j++) {
            int c = tx * 4 + j;
            C[(size_t)row * D_ + h * 64 + c] = acc[i][j] + bias[h * 64 + c];
        }
    }
}

// =================================================================
// Trans-B GEMM:  C = A[M,K] * W^T  (+bias, optional relu, residual)
// W: [N, K] row-major. Grid: (M/64, N/64). 256 threads.
// =================================================================
__global__ __launch_bounds__(256) void gemm_tb(
    const float* __restrict__ A, const float* __restrict__ W,
    const float* __restrict__ bias, const float* __restrict__ residual,
    float* __restrict__ C, int N, int K, int relu)
{
    const int m0 = blockIdx.x * 64;
    const int n0 = blockIdx.y * 64;
    __shared__ float As[16][68];
    __shared__ float Bs[16][68];

    const int tid = threadIdx.x;
    const int tx = tid & 15, ty = tid >> 4;
    float acc[4][4] = {};

    for (int kk = 0; kk < K; kk += 16) {
        {
            int row = tid >> 2, k4 = (tid & 3) * 4;
            float4 a = *(const float4*)(A + (size_t)(m0 + row) * K + kk + k4);
            As[k4 + 0][row] = a.x; As[k4 + 1][row] = a.y;
            As[k4 + 2][row] = a.z; As[k4 + 3][row] = a.w;
        }
        {
            int n = tid >> 2, k4 = (tid & 3) * 4;
            float4 w = *(const float4*)(W + (size_t)(n0 + n) * K + kk + k4);
            Bs[k4 + 0][n] = w.x; Bs[k4 + 1][n] = w.y;
            Bs[k4 + 2][n] = w.z; Bs[k4 + 3][n] = w.w;
        }
        __syncthreads();
        #pragma unroll
        for (int k = 0; k < 16; k++) {
            float4 av = *(const float4*)&As[k][ty * 4];
            float4 bv = *(const float4*)&Bs[k][tx * 4];
            float a[4] = {av.x, av.y, av.z, av.w};
            float b[4] = {bv.x, bv.y, bv.z, bv.w};
            #pragma unroll
            for (int i = 0; i < 4; i++)
                #pragma unroll
                for (int j = 0; j < 4; j++)
                    acc[i][j] += a[i] * b[j];
        }
        __syncthreads();
    }
    #pragma unroll
    for (int i = 0; i < 4; i++) {
        int row = m0 + ty * 4 + i;
        #pragma unroll
        for (int j = 0; j < 4; j++) {
            int col = n0 + tx * 4 + j;
            float v = acc[i][j] + bias[col];
            if (relu) v = fmaxf(v, 0.0f);
            size_t idx = (size_t)row * N + col;
            if (residual) v += residual[idx];
            C[idx] = v;
        }
    }
}

// =================================================================
// Attention: block = (q-tile of 16 rows, h, b). 256 threads.
// Q/K/V layout [B*S, H*64] (col = h*64+d). Output same layout.
// =================================================================
#define SMEM_ATTN ((16 * 64 + 64 * 68 + 16 * 1024 + 16) * 4)

__global__ __launch_bounds__(256) void attn_kernel(
    const float* __restrict__ Q, const float* __restrict__ K,
    const float* __restrict__ V, const int* __restrict__ mask,
    float* __restrict__ O)
{
    const int qt = blockIdx.x;          // 0..63  (16 q-rows each)
    const int h  = blockIdx.y;
    const int b  = blockIdx.z;

    extern __shared__ float sm[];
    float* Qs     = sm;                         // 16*64
    float* KV     = sm + 16 * 64;               // 64*68
    float* Sc     = sm + 16 * 64 + 64 * 68;     // 16*1024
    float* rowinv = Sc + 16 * 1024;             // 16

    const int tid = threadIdx.x;
    const float scale = 0.125f;                 // 1/sqrt(64)

    {   // load 16x64 Q tile (256 float4 = exactly 256 threads)
        int r = tid >> 4, d4 = (tid & 15) * 4;
        *(float4*)&Qs[r * 64 + d4] =
            *(const float4*)(Q + (size_t)(b * S_ + qt * 16 + r) * D_ + h * 64 + d4);
    }

    const int key = tid >> 2;            // 0..63
    const int dq  = (tid & 3) * 4;       // base quad within 16-dim group

    // ---- scores ----
    for (int kc = 0; kc < 16; kc++) {
        // full 64x64 K tile: each thread loads 4 float4 (dims dq+16*i)
        float4 kvr[4];
        const float* Krow = K + (size_t)(b * S_ + kc * 64 + key) * D_ + h * 64;
        #pragma unroll
        for (int i = 0; i < 4; i++)
            kvr[i] = *(const float4*)(Krow + dq + 16 * i);
        __syncthreads();
        #pragma unroll
        for (int i = 0; i < 4; i++)
            *(float4*)&KV[key * 68 + dq + 16 * i] = kvr[i];
        __syncthreads();

        int k = tid & 63, rb = tid >> 6;
        #pragma unroll
        for (int rr = 0; rr < 4; rr++) {
            int r = rb + rr * 4;
            float dot = 0.0f;
            #pragma unroll
            for (int d = 0; d < 64; d += 4) {
                float4 qv = *(const float4*)&Qs[r * 64 + d];
                float4 kk2 = *(const float4*)&KV[k * 68 + d];
                dot += qv.x * kk2.x + qv.y * kk2.y + qv.z * kk2.z + qv.w * kk2.w;
            }
            int kg = kc * 64 + k;
            float s = (mask[b * S_ + kg] != 0) ? dot * scale : -1e10f;
            Sc[r * 1024 + kg] = s;
        }
    }
    __syncthreads();

    // ---- softmax: warp w handles rows 2w, 2w+1 ----
    int warp = tid >> 5, lane = tid & 31;
    for (int rw = 0; rw < 2; rw++) {
        int r = warp * 2 + rw;
        float m = -1e30f;
        for (int j = lane; j < 1024; j += 32) m = fmaxf(m, Sc[r * 1024 + j]);
        #pragma unroll
        for (int o = 16; o; o >>= 1) m = fmaxf(m, __shfl_xor_sync(0xffffffffu, m, o));
        float ssum = 0.0f;
        for (int j = lane; j < 1024; j += 32) {
            float e = __expf(Sc[r * 1024 + j] - m);
            Sc[r * 1024 + j] = e;
            ssum += e;
        }
        #pragma unroll
        for (int o = 16; o; o >>= 1) ssum += __shfl_xor_sync(0xffffffffu, ssum, o);
        if (lane == 0) rowinv[r] = 1.0f / ssum;
    }
    __syncthreads();

    // ---- A*V: thread owns (row r, 4 cols d4b) ----
    float4 acc = {0.f, 0.f, 0.f, 0.f};
    const int r = tid >> 4, d4b = (tid & 15) * 4;
    for (int vc = 0; vc < 16; vc++) {
        // full 64x64 V tile: each thread loads 4 float4
        float4 vvr[4];
        const float* Vrow = V + (size_t)(b * S_ + vc * 64 + key) * D_ + h * 64;
        #pragma unroll
        for (int i = 0; i < 4; i++)
            vvr[i] = *(const float4*)(Vrow + dq + 16 * i);
        __syncthreads();
        #pragma unroll
        for (int i = 0; i < 4; i++)
            *(float4*)&KV[key * 68 + dq + 16 * i] = vvr[i];
        __syncthreads();

        #pragma unroll 8
        for (int j = 0; j < 64; j++) {
            float p = Sc[r * 1024 + vc * 64 + j];
            float4 v4 = *(const float4*)&KV[j * 68 + d4b];
            acc.x += p * v4.x; acc.y += p * v4.y;
            acc.z += p * v4.z; acc.w += p * v4.w;
        }
    }
    float inv = rowinv[r];
    float4 o4 = {acc.x * inv, acc.y * inv, acc.z * inv, acc.w * inv};
    *(float4*)(O + (size_t)(b * S_ + qt * 16 + r) * D_ + h * 64 + d4b) = o4;
}

// =================================================================
// LayerNorm over the whole [S, D] slab per batch sample.
// =================================================================
__global__ __launch_bounds__(1024) void ln_reduce(const float* __restrict__ X,
                                                  float* __restrict__ stats)
{
    const int b = blockIdx.x;
    const float* x = X + (size_t)b * S_ * D_;
    double s = 0.0, s2 = 0.0;
    for (int i = threadIdx.x; i < S_ * D_; i += 1024) {
        float v = x[i];
        s += v; s2 += (double)v * v;
    }
    __shared__ double sh[1024], sh2[1024];
    sh[threadIdx.x] = s; sh2[threadIdx.x] = s2;
    __syncthreads();
    for (int st = 512; st; st >>= 1) {
        if (threadIdx.x < st) {
            sh[threadIdx.x]  += sh[threadIdx.x + st];
            sh2[threadIdx.x] += sh2[threadIdx.x + st];
        }
        __syncthreads();
    }
    if (threadIdx.x == 0) {
        double n = (double)(S_ * D_);
        double mean = sh[0] / n;
        double var  = sh2[0] / n - mean * mean;
        stats[b * 2 + 0] = (float)mean;
        stats[b * 2 + 1] = (float)rsqrt(var + 1e-6);
    }
}

__global__ __launch_bounds__(256) void ln_apply(
    const float* __restrict__ X, const float* __restrict__ w,
    const float* __restrict__ bias, const float* __restrict__ stats,
    float* __restrict__ Out)
{
    int i = blockIdx.x * 256 + threadIdx.x;          // over B*S*D
    int b  = i / (S_ * D_);
    int sd = i - b * (S_ * D_);
    float mean = stats[b * 2], rstd = stats[b * 2 + 1];
    Out[i] = (X[i] - mean) * rstd * w[sd] + bias[sd];
}

// =================================================================
extern "C" void kernel_launch(void* const* d_in, const int* in_sizes, int n_in,
                              void* d_out, int out_size)
{
    const float* x        = (const float*)d_in[0];
    const float* y        = (const float*)d_in[1];
    const int*   src_mask = (const int*)  d_in[2];
    const int*   trg_mask = (const int*)  d_in[3];
    const float* m1_wq = (const float*)d_in[4];
    const float* m1_bq = (const float*)d_in[5];
    const float* m1_wk = (const float*)d_in[6];
    const float* m1_bk = (const float*)d_in[7];
    const float* m1_wv = (const float*)d_in[8];
    const float* m1_bv = (const float*)d_in[9];
    const float* m1_wo = (const float*)d_in[10];
    const float* m1_bo = (const float*)d_in[11];
    const float* m2_wq = (const float*)d_in[12];
    const float* m2_bq = (const float*)d_in[13];
    const float* m2_wk = (const float*)d_in[14];
    const float* m2_bk = (const float*)d_in[15];
    const float* m2_wv = (const float*)d_in[16];
    const float* m2_bv = (const float*)d_in[17];
    const float* m2_wo = (const float*)d_in[18];
    const float* m2_bo = (const float*)d_in[19];
    const float* pw1   = (const float*)d_in[20];
    const float* pb1   = (const float*)d_in[21];
    const float* pw2   = (const float*)d_in[22];
    const float* pb2   = (const float*)d_in[23];
    const float* ln1_w = (const float*)d_in[24];
    const float* ln1_b = (const float*)d_in[25];
    const float* ln2_w = (const float*)d_in[26];
    const float* ln2_b = (const float*)d_in[27];
    const float* ln3_w = (const float*)d_in[28];
    const float* ln3_b = (const float*)d_in[29];
    float* out = (float*)d_out;

    float *q, *k, *v, *attn, *res, *x1, *x2, *ff, *stats;
    cudaGetSymbolAddress((void**)&q,     g_q);
    cudaGetSymbolAddress((void**)&k,     g_k);
    cudaGetSymbolAddress((void**)&v,     g_v);
    cudaGetSymbolAddress((void**)&attn,  g_attn);
    cudaGetSymbolAddress((void**)&res,   g_res);
    cudaGetSymbolAddress((void**)&x1,    g_x1);
    cudaGetSymbolAddress((void**)&x2,    g_x2);
    cudaGetSymbolAddress((void**)&ff,    g_ff);
    cudaGetSymbolAddress((void**)&stats, g_stats);

    cudaFuncSetAttribute(attn_kernel,
                         cudaFuncAttributeMaxDynamicSharedMemorySize, SMEM_ATTN);

    const dim3 gProj(BS_ / 64, 1, H_);
    const dim3 gAttn(S_ / 16, H_, B_);

    // ---- self-attention ----
    gemm_head<<<gProj, 256>>>(x, m1_wq, m1_bq, q);
    gemm_head<<<gProj, 256>>>(x, m1_wk, m1_bk, k);
    gemm_head<<<gProj, 256>>>(x, m1_wv, m1_bv, v);
    attn_kernel<<<gAttn, 256, SMEM_ATTN>>>(q, k, v, trg_mask, attn);
    gemm_tb<<<dim3(BS_ / 64, D_ / 64), 256>>>(attn, m1_wo, m1_bo, x, res, D_, D_, 0);
    ln_reduce<<<B_, 1024>>>(res, stats);
    ln_apply<<<BS_ * D_ / 256, 256>>>(res, ln1_w, ln1_b, stats, x1);

    // ---- cross-attention ----
    gemm_head<<<gProj, 256>>>(x1, m2_wq, m2_bq, q);
    gemm_head<<<gProj, 256>>>(y,  m2_wk, m2_bk, k);
    gemm_head<<<gProj, 256>>>(y,  m2_wv, m2_bv, v);
    attn_kernel<<<gAttn, 256, SMEM_ATTN>>>(q, k, v, src_mask, attn);
    gemm_tb<<<dim3(BS_ / 64, D_ / 64), 256>>>(attn, m2_wo, m2_bo, x1, res, D_, D_, 0);
    ln_reduce<<<B_, 1024>>>(res, stats);
    ln_apply<<<BS_ * D_ / 256, 256>>>(res, ln2_w, ln2_b, stats, x2);

    // ---- FFN ----
    gemm_tb<<<dim3(BS_ / 64, DFF_ / 64), 256>>>(x2, pw1, pb1, nullptr, ff, DFF_, D_, 1);
    gemm_tb<<<dim3(BS_ / 64, D_ / 64),  256>>>(ff, pw2, pb2, x2, res, D_, DFF_, 0);
    ln_reduce<<<B_, 1024>>>(res, stats);
    ln_apply<<<BS_ * D_ / 256, 256>>>(res, ln3_w, ln3_b, stats, out);
}

// round 6
// speedup vs baseline: 2.0396x; 2.0396x over previous
#include <cuda_runtime.h>

#define B_   8
#define S_   1024
#define D_   512
#define H_   8
#define DFF_ 2048
#define BS_  (B_ * S_)

// ---------------- scratch (no allocations allowed) ----------------
__device__ float g_q[BS_ * D_];
__device__ float g_k[BS_ * D_];
__device__ float g_v[BS_ * D_];
__device__ float g_attn[BS_ * D_];
__device__ float g_res[BS_ * D_];
__device__ float g_x1[BS_ * D_];
__device__ float g_x2[BS_ * D_];
__device__ float g_ff[BS_ * DFF_];
__device__ float g_part[256];      // 128 blocks x {sum, sumsq}
__device__ float g_stats[2 * B_];  // {mean, rstd} per sample

// =================================================================
// Trans-B GEMM: C = A[M,K] * W^T (+bias, opt relu, opt residual)
// W: [N,K] row-major. 128x128 tile, 256 threads, 8x8 per thread.
// =================================================================
__global__ __launch_bounds__(256) void gemm_tb(
    const float* __restrict__ A, const float* __restrict__ W,
    const float* __restrict__ bias, const float* __restrict__ residual,
    float* __restrict__ C, int N, int K, int relu)
{
    const int m0 = blockIdx.x * 128;
    const int n0 = blockIdx.y * 128;
    __shared__ float As[16][132];
    __shared__ float Bs[16][132];

    const int tid = threadIdx.x;
    const int tx = tid & 15, ty = tid >> 4;
    float acc[8][8] = {};

    for (int kk = 0; kk < K; kk += 16) {
        #pragma unroll
        for (int it = 0; it < 2; it++) {
            int t = tid + it * 256;
            int row = t >> 2, kq = (t & 3) * 4;
            float4 a = *(const float4*)(A + (size_t)(m0 + row) * K + kk + kq);
            As[kq + 0][row] = a.x; As[kq + 1][row] = a.y;
            As[kq + 2][row] = a.z; As[kq + 3][row] = a.w;
            float4 w = *(const float4*)(W + (size_t)(n0 + row) * K + kk + kq);
            Bs[kq + 0][row] = w.x; Bs[kq + 1][row] = w.y;
            Bs[kq + 2][row] = w.z; Bs[kq + 3][row] = w.w;
        }
        __syncthreads();
        #pragma unroll
        for (int k = 0; k < 16; k++) {
            float4 a0 = *(const float4*)&As[k][ty * 8];
            float4 a1 = *(const float4*)&As[k][ty * 8 + 4];
            float4 b0 = *(const float4*)&Bs[k][tx * 8];
            float4 b1 = *(const float4*)&Bs[k][tx * 8 + 4];
            float av[8] = {a0.x, a0.y, a0.z, a0.w, a1.x, a1.y, a1.z, a1.w};
            float bv[8] = {b0.x, b0.y, b0.z, b0.w, b1.x, b1.y, b1.z, b1.w};
            #pragma unroll
            for (int i = 0; i < 8; i++)
                #pragma unroll
                for (int j = 0; j < 8; j++)
                    acc[i][j] += av[i] * bv[j];
        }
        __syncthreads();
    }
    #pragma unroll
    for (int i = 0; i < 8; i++) {
        int row = m0 + ty * 8 + i;
        #pragma unroll
        for (int jq = 0; jq < 2; jq++) {
            int col = n0 + tx * 8 + jq * 4;
            size_t idx = (size_t)row * N + col;
            float4 v;
            v.x = acc[i][jq * 4 + 0] + bias[col + 0];
            v.y = acc[i][jq * 4 + 1] + bias[col + 1];
            v.z = acc[i][jq * 4 + 2] + bias[col + 2];
            v.w = acc[i][jq * 4 + 3] + bias[col + 3];
            if (relu) {
                v.x = fmaxf(v.x, 0.f); v.y = fmaxf(v.y, 0.f);
                v.z = fmaxf(v.z, 0.f); v.w = fmaxf(v.w, 0.f);
            }
            if (residual) {
                float4 r = *(const float4*)(residual + idx);
                v.x += r.x; v.y += r.y; v.z += r.z; v.w += r.w;
            }
            *(float4*)(C + idx) = v;
        }
    }
}

// =================================================================
// Per-head projection GEMM: C[n, h*64+c] = sum_d A[n,d]*W[h,d,c] + b
// 128x64 tile (one head), 256 threads, 8x4 per thread.
// =================================================================
__global__ __launch_bounds__(256) void gemm_head(
    const float* __restrict__ A, const float* __restrict__ W,
    const float* __restrict__ bias, float* __restrict__ C)
{
    const int h  = blockIdx.z;
    const int m0 = blockIdx.x * 128;
    __shared__ float As[16][132];
    __shared__ float Bs[16][68];

    const int tid = threadIdx.x;
    const int tx = tid & 15, ty = tid >> 4;
    float acc[8][4] = {};

    const float* Wh = W + (size_t)h * (D_ * 64);

    for (int kk = 0; kk < D_; kk += 16) {
        #pragma unroll
        for (int it = 0; it < 2; it++) {
            int t = tid + it * 256;
            int row = t >> 2, kq = (t & 3) * 4;
            float4 a = *(const float4*)(A + (size_t)(m0 + row) * D_ + kk + kq);
            As[kq + 0][row] = a.x; As[kq + 1][row] = a.y;
            As[kq + 2][row] = a.z; As[kq + 3][row] = a.w;
        }
        {   // B tile: 16 k x 64 n, direct float4 copy
            int k = tid >> 4, n4 = (tid & 15) * 4;
            *(float4*)&Bs[k][n4] = *(const float4*)(Wh + (size_t)(kk + k) * 64 + n4);
        }
        __syncthreads();
        #pragma unroll
        for (int k = 0; k < 16; k++) {
            float4 a0 = *(const float4*)&As[k][ty * 8];
            float4 a1 = *(const float4*)&As[k][ty * 8 + 4];
            float4 b  = *(const float4*)&Bs[k][tx * 4];
            float av[8] = {a0.x, a0.y, a0.z, a0.w, a1.x, a1.y, a1.z, a1.w};
            float bv[4] = {b.x, b.y, b.z, b.w};
            #pragma unroll
            for (int i = 0; i < 8; i++)
                #pragma unroll
                for (int j = 0; j < 4; j++)
                    acc[i][j] += av[i] * bv[j];
        }
        __syncthreads();
    }
    #pragma unroll
    for (int i = 0; i < 8; i++) {
        int row = m0 + ty * 8 + i;
        int col = h * 64 + tx * 4;
        float4 v;
        v.x = acc[i][0] + bias[col + 0];
        v.y = acc[i][1] + bias[col + 1];
        v.z = acc[i][2] + bias[col + 2];
        v.w = acc[i][3] + bias[col + 3];
        *(float4*)(C + (size_t)row * D_ + col) = v;
    }
}

// =================================================================
// Flash attention: block = (64 q-rows, h, b). 256 threads.
// Online softmax, 4x4 register tiles for QK^T and PV.
// Qt/Kt dim-major, Vs/Pt key-major; all compute LDS conflict-free.
// =================================================================
#define AT_SMEM ((4 * 64 * 68 + 1024) * 4)

__global__ __launch_bounds__(256) void attn_kernel(
    const float* __restrict__ Q, const float* __restrict__ K,
    const float* __restrict__ V, const int* __restrict__ mask,
    float* __restrict__ O)
{
    const int qt = blockIdx.x;          // 0..15 (64 q-rows each)
    const int h  = blockIdx.y;
    const int b  = blockIdx.z;

    extern __shared__ float sm[];
    float* Qt  = sm;                 // [d][r]   stride 68
    float* Kt  = sm + 64 * 68;       // [d][key] stride 68
    float* Vs  = sm + 2 * 64 * 68;   // [key][d] stride 68
    float* Pt  = sm + 3 * 64 * 68;   // [key][r] stride 68
    float* msk = sm + 4 * 64 * 68;   // [1024]

    const int tid = threadIdx.x;
    const int tx = tid & 15, ty = tid >> 4;
    const float scale = 0.125f;      // 1/sqrt(64)

    // ---- load Q (transposed) + mask flags ----
    #pragma unroll
    for (int it = 0; it < 4; it++) {
        int t = tid + it * 256;
        int r = t >> 4, d4 = (t & 15) * 4;
        float4 qv = *(const float4*)(Q + (size_t)(b * S_ + qt * 64 + r) * D_ + h * 64 + d4);
        Qt[(d4 + 0) * 68 + r] = qv.x; Qt[(d4 + 1) * 68 + r] = qv.y;
        Qt[(d4 + 2) * 68 + r] = qv.z; Qt[(d4 + 3) * 68 + r] = qv.w;
        msk[t] = (mask[b * S_ + t] != 0) ? 1.0f : 0.0f;
    }

    float acc[4][4] = {};
    float m_run[4], l_run[4];
    #pragma unroll
    for (int i = 0; i < 4; i++) { m_run[i] = -1e30f; l_run[i] = 0.0f; }

    for (int kc = 0; kc < 16; kc++) {
        __syncthreads();   // previous iter's consumers done before overwrite
        #pragma unroll
        for (int it = 0; it < 4; it++) {
            int t = tid + it * 256;
            int key = t >> 4, d4 = (t & 15) * 4;
            const float* base = K + (size_t)(b * S_ + kc * 64 + key) * D_ + h * 64;
            float4 kv = *(const float4*)(base + d4);
            Kt[(d4 + 0) * 68 + key] = kv.x; Kt[(d4 + 1) * 68 + key] = kv.y;
            Kt[(d4 + 2) * 68 + key] = kv.z; Kt[(d4 + 3) * 68 + key] = kv.w;
            float4 vv = *(const float4*)(V + (size_t)(b * S_ + kc * 64 + key) * D_ + h * 64 + d4);
            *(float4*)&Vs[key * 68 + d4] = vv;
        }
        __syncthreads();

        // ---- scores: s[4 rows][4 keys] ----
        float s[4][4] = {};
        #pragma unroll 8
        for (int d = 0; d < 64; d++) {
            float4 q4 = *(const float4*)&Qt[d * 68 + ty * 4];
            float4 k4 = *(const float4*)&Kt[d * 68 + tx * 4];
            float qa[4] = {q4.x, q4.y, q4.z, q4.w};
            float ka[4] = {k4.x, k4.y, k4.z, k4.w};
            #pragma unroll
            for (int i = 0; i < 4; i++)
                #pragma unroll
                for (int j = 0; j < 4; j++)
                    s[i][j] += qa[i] * ka[j];
        }
        // mask + scale
        #pragma unroll
        for (int j = 0; j < 4; j++) {
            float mm = msk[kc * 64 + tx * 4 + j];
            #pragma unroll
            for (int i = 0; i < 4; i++)
                s[i][j] = (mm != 0.0f) ? s[i][j] * scale : -1e10f;
        }
        // ---- online softmax (row reduce across 16-lane half-warp) ----
        #pragma unroll
        for (int i = 0; i < 4; i++) {
            float mc = fmaxf(fmaxf(s[i][0], s[i][1]), fmaxf(s[i][2], s[i][3]));
            mc = fmaxf(mc, __shfl_xor_sync(0xffffffffu, mc, 1));
            mc = fmaxf(mc, __shfl_xor_sync(0xffffffffu, mc, 2));
            mc = fmaxf(mc, __shfl_xor_sync(0xffffffffu, mc, 4));
            mc = fmaxf(mc, __shfl_xor_sync(0xffffffffu, mc, 8));
            float mn = fmaxf(m_run[i], mc);
            float sc = __expf(m_run[i] - mn);
            m_run[i] = mn;
            float ls = 0.0f;
            #pragma unroll
            for (int j = 0; j < 4; j++) {
                float p = __expf(s[i][j] - mn);
                s[i][j] = p;
                ls += p;
            }
            ls += __shfl_xor_sync(0xffffffffu, ls, 1);
            ls += __shfl_xor_sync(0xffffffffu, ls, 2);
            ls += __shfl_xor_sync(0xffffffffu, ls, 4);
            ls += __shfl_xor_sync(0xffffffffu, ls, 8);
            l_run[i] = l_run[i] * sc + ls;
            #pragma unroll
            for (int j = 0; j < 4; j++) acc[i][j] *= sc;
        }
        // ---- write P (transposed: [key][row]) ----
        #pragma unroll
        for (int j = 0; j < 4; j++)
            #pragma unroll
            for (int i = 0; i < 4; i++)
                Pt[(tx * 4 + j) * 68 + ty * 4 + i] = s[i][j];
        __syncthreads();
        // ---- acc += P^T tile * V tile ----
        #pragma unroll 8
        for (int k = 0; k < 64; k++) {
            float4 p4 = *(const float4*)&Pt[k * 68 + ty * 4];
            float4 v4 = *(const float4*)&Vs[k * 68 + tx * 4];
            float pa[4] = {p4.x, p4.y, p4.z, p4.w};
            float va[4] = {v4.x, v4.y, v4.z, v4.w};
            #pragma unroll
            for (int i = 0; i < 4; i++)
                #pragma unroll
                for (int j = 0; j < 4; j++)
                    acc[i][j] += pa[i] * va[j];
        }
    }

    // ---- output ----
    #pragma unroll
    for (int i = 0; i < 4; i++) {
        float inv = 1.0f / l_run[i];
        float4 o;
        o.x = acc[i][0] * inv; o.y = acc[i][1] * inv;
        o.z = acc[i][2] * inv; o.w = acc[i][3] * inv;
        *(float4*)(O + (size_t)(b * S_ + qt * 64 + ty * 4 + i) * D_ + h * 64 + tx * 4) = o;
    }
}

// =================================================================
// LayerNorm over [S,D] slab per sample: fp32 partial sums,
// 16 blocks per sample + tiny finalize.
// =================================================================
__global__ __launch_bounds__(256) void ln_partial(const float* __restrict__ X,
                                                  float* __restrict__ part)
{
    const int b = blockIdx.x >> 4, seg = blockIdx.x & 15;
    const float4* x = (const float4*)(X + (size_t)b * S_ * D_ + seg * 32768);
    float s = 0.f, s2 = 0.f;
    #pragma unroll 4
    for (int i = threadIdx.x; i < 8192; i += 256) {
        float4 v = x[i];
        s  += v.x + v.y + v.z + v.w;
        s2 += v.x * v.x + v.y * v.y + v.z * v.z + v.w * v.w;
    }
    #pragma unroll
    for (int o = 16; o; o >>= 1) {
        s  += __shfl_xor_sync(0xffffffffu, s, o);
        s2 += __shfl_xor_sync(0xffffffffu, s2, o);
    }
    __shared__ float ws[8], ws2[8];
    int lane = threadIdx.x & 31, wp = threadIdx.x >> 5;
    if (lane == 0) { ws[wp] = s; ws2[wp] = s2; }
    __syncthreads();
    if (threadIdx.x == 0) {
        float a = 0.f, a2 = 0.f;
        #pragma unroll
        for (int w = 0; w < 8; w++) { a += ws[w]; a2 += ws2[w]; }
        part[blockIdx.x * 2 + 0] = a;
        part[blockIdx.x * 2 + 1] = a2;
    }
}

__global__ void ln_finalize(const float* __restrict__ part, float* __restrict__ stats)
{
    int b = threadIdx.x;
    if (b < B_) {
        float s = 0.f, s2 = 0.f;
        for (int k = 0; k < 16; k++) {
            s  += part[(b * 16 + k) * 2 + 0];
            s2 += part[(b * 16 + k) * 2 + 1];
        }
        const float inv_n = 1.0f / (float)(S_ * D_);
        float mean = s * inv_n;
        float var  = s2 * inv_n - mean * mean;
        stats[b * 2 + 0] = mean;
        stats[b * 2 + 1] = rsqrtf(var + 1e-6f);
    }
}

__global__ __launch_bounds__(256) void ln_apply(
    const float* __restrict__ X, const float* __restrict__ w,
    const float* __restrict__ bias, const float* __restrict__ stats,
    float* __restrict__ Out)
{
    int i = blockIdx.x * 256 + threadIdx.x;      // float4 index over B*S*D/4
    int b  = i >> 17;                            // 131072 float4 per sample
    int sd = i - (b << 17);
    float mean = stats[b * 2], rstd = stats[b * 2 + 1];
    float4 xv = ((const float4*)X)[i];
    float4 wv = ((const float4*)w)[sd];
    float4 bv = ((const float4*)bias)[sd];
    float4 o;
    o.x = (xv.x - mean) * rstd * wv.x + bv.x;
    o.y = (xv.y - mean) * rstd * wv.y + bv.y;
    o.z = (xv.z - mean) * rstd * wv.z + bv.z;
    o.w = (xv.w - mean) * rstd * wv.w + bv.w;
    ((float4*)Out)[i] = o;
}

// =================================================================
extern "C" void kernel_launch(void* const* d_in, const int* in_sizes, int n_in,
                              void* d_out, int out_size)
{
    const float* x        = (const float*)d_in[0];
    const float* y        = (const float*)d_in[1];
    const int*   src_mask = (const int*)  d_in[2];
    const int*   trg_mask = (const int*)  d_in[3];
    const float* m1_wq = (const float*)d_in[4];
    const float* m1_bq = (const float*)d_in[5];
    const float* m1_wk = (const float*)d_in[6];
    const float* m1_bk = (const float*)d_in[7];
    const float* m1_wv = (const float*)d_in[8];
    const float* m1_bv = (const float*)d_in[9];
    const float* m1_wo = (const float*)d_in[10];
    const float* m1_bo = (const float*)d_in[11];
    const float* m2_wq = (const float*)d_in[12];
    const float* m2_bq = (const float*)d_in[13];
    const float* m2_wk = (const float*)d_in[14];
    const float* m2_bk = (const float*)d_in[15];
    const float* m2_wv = (const float*)d_in[16];
    const float* m2_bv = (const float*)d_in[17];
    const float* m2_wo = (const float*)d_in[18];
    const float* m2_bo = (const float*)d_in[19];
    const float* pw1   = (const float*)d_in[20];
    const float* pb1   = (const float*)d_in[21];
    const float* pw2   = (const float*)d_in[22];
    const float* pb2   = (const float*)d_in[23];
    const float* ln1_w = (const float*)d_in[24];
    const float* ln1_b = (const float*)d_in[25];
    const float* ln2_w = (const float*)d_in[26];
    const float* ln2_b = (const float*)d_in[27];
    const float* ln3_w = (const float*)d_in[28];
    const float* ln3_b = (const float*)d_in[29];
    float* out = (float*)d_out;

    float *q, *k, *v, *attn, *res, *x1, *x2, *ff, *part, *stats;
    cudaGetSymbolAddress((void**)&q,     g_q);
    cudaGetSymbolAddress((void**)&k,     g_k);
    cudaGetSymbolAddress((void**)&v,     g_v);
    cudaGetSymbolAddress((void**)&attn,  g_attn);
    cudaGetSymbolAddress((void**)&res,   g_res);
    cudaGetSymbolAddress((void**)&x1,    g_x1);
    cudaGetSymbolAddress((void**)&x2,    g_x2);
    cudaGetSymbolAddress((void**)&ff,    g_ff);
    cudaGetSymbolAddress((void**)&part,  g_part);
    cudaGetSymbolAddress((void**)&stats, g_stats);

    cudaFuncSetAttribute(attn_kernel,
                         cudaFuncAttributeMaxDynamicSharedMemorySize, AT_SMEM);

    const dim3 gProj(BS_ / 128, 1, H_);
    const dim3 gAttn(S_ / 64, H_, B_);
    const int  gApply = (BS_ * D_ / 4) / 256;

    // ---- self-attention ----
    gemm_head<<<gProj, 256>>>(x, m1_wq, m1_bq, q);
    gemm_head<<<gProj, 256>>>(x, m1_wk, m1_bk, k);
    gemm_head<<<gProj, 256>>>(x, m1_wv, m1_bv, v);
    attn_kernel<<<gAttn, 256, AT_SMEM>>>(q, k, v, trg_mask, attn);
    gemm_tb<<<dim3(BS_ / 128, D_ / 128), 256>>>(attn, m1_wo, m1_bo, x, res, D_, D_, 0);
    ln_partial<<<16 * B_, 256>>>(res, part);
    ln_finalize<<<1, 32>>>(part, stats);
    ln_apply<<<gApply, 256>>>(res, ln1_w, ln1_b, stats, x1);

    // ---- cross-attention ----
    gemm_head<<<gProj, 256>>>(x1, m2_wq, m2_bq, q);
    gemm_head<<<gProj, 256>>>(y,  m2_wk, m2_bk, k);
    gemm_head<<<gProj, 256>>>(y,  m2_wv, m2_bv, v);
    attn_kernel<<<gAttn, 256, AT_SMEM>>>(q, k, v, src_mask, attn);
    gemm_tb<<<dim3(BS_ / 128, D_ / 128), 256>>>(attn, m2_wo, m2_bo, x1, res, D_, D_, 0);
    ln_partial<<<16 * B_, 256>>>(res, part);
    ln_finalize<<<1, 32>>>(part, stats);
    ln_apply<<<gApply, 256>>>(res, ln2_w, ln2_b, stats, x2);

    // ---- FFN ----
    gemm_tb<<<dim3(BS_ / 128, DFF_ / 128), 256>>>(x2, pw1, pb1, nullptr, ff, DFF_, D_, 1);
    gemm_tb<<<dim3(BS_ / 128, D_ / 128),  256>>>(ff, pw2, pb2, x2, res, D_, DFF_, 0);
    ln_partial<<<16 * B_, 256>>>(res, part);
    ln_finalize<<<1, 32>>>(part, stats);
    ln_apply<<<gApply, 256>>>(res, ln3_w, ln3_b, stats, out);
}

// round 8
// speedup vs baseline: 2.7902x; 1.3680x over previous
#include <cuda_runtime.h>
#include <cuda_bf16.h>
#include <cstdint>

#define B_   8
#define S_   1024
#define D_   512
#define H_   8
#define DFF_ 2048
#define BS_  (B_ * S_)

// ---------------- scratch (no allocations allowed) ----------------
__device__ float g_q[BS_ * D_];
__device__ float g_k[BS_ * D_];
__device__ float g_v[BS_ * D_];
__device__ float g_attn[BS_ * D_];
__device__ float g_res[BS_ * D_];
__device__ float g_x1[BS_ * D_];
__device__ float g_x2[BS_ * D_];
__device__ float g_ff[BS_ * DFF_];
__device__ float g_part[256];
__device__ float g_stats[2 * B_];
// bf16 split operand buffers
__device__ unsigned short g_ah[BS_ * DFF_];   // activation hi (max 8192x2048)
__device__ unsigned short g_al[BS_ * DFF_];   // activation lo
__device__ unsigned short g_wh[DFF_ * D_];    // weight hi (max 2048x512)
__device__ unsigned short g_wl[DFF_ * D_];    // weight lo

// ---------------- helpers ----------------
static __device__ __forceinline__ unsigned short bfu(float x) {
    __nv_bfloat16 h = __float2bfloat16(x);
    return *reinterpret_cast<unsigned short*>(&h);
}
static __device__ __forceinline__ float ubf(unsigned short u) {
    __nv_bfloat16 h = *reinterpret_cast<__nv_bfloat16*>(&u);
    return __bfloat162float(h);
}
static __device__ __forceinline__ uint32_t smem_u32(const void* p) {
    uint32_t a;
    asm("{ .reg .u64 t; cvta.to.shared.u64 t, %1; cvt.u32.u64 %0, t; }"
        : "=r"(a) : "l"(p));
    return a;
}
static __device__ __forceinline__ void ldsm4(uint32_t* r, uint32_t addr) {
    asm volatile("ldmatrix.sync.aligned.m8n8.x4.shared.b16 {%0,%1,%2,%3}, [%4];"
        : "=r"(r[0]), "=r"(r[1]), "=r"(r[2]), "=r"(r[3]) : "r"(addr));
}
static __device__ __forceinline__ void mma16816(
    float* c, const uint32_t* a, const uint32_t* b)
{
    asm volatile(
        "mma.sync.aligned.m16n8k16.row.col.f32.bf16.bf16.f32 "
        "{%0,%1,%2,%3}, {%4,%5,%6,%7}, {%8,%9}, {%0,%1,%2,%3};"
        : "+f"(c[0]), "+f"(c[1]), "+f"(c[2]), "+f"(c[3])
        : "r"(a[0]), "r"(a[1]), "r"(a[2]), "r"(a[3]), "r"(b[0]), "r"(b[1]));
}

// =================================================================
// Operand conversion: fp32 -> bf16 hi + bf16 lo
// =================================================================
__global__ __launch_bounds__(256) void cvt_split(
    const float* __restrict__ in, unsigned short* __restrict__ hi,
    unsigned short* __restrict__ lo, int n4)
{
    int i = blockIdx.x * 256 + threadIdx.x;
    if (i >= n4) return;
    float4 v = ((const float4*)in)[i];
    ushort4 H, L;
    H.x = bfu(v.x); L.x = bfu(v.x - ubf(H.x));
    H.y = bfu(v.y); L.y = bfu(v.y - ubf(H.y));
    H.z = bfu(v.z); L.z = bfu(v.z - ubf(H.z));
    H.w = bfu(v.w); L.w = bfu(v.w - ubf(H.w));
    ((ushort4*)hi)[i] = H;
    ((ushort4*)lo)[i] = L;
}

// Head weights [H, D, 64] -> trans-B layout [N=512, K=512] hi/lo
__global__ __launch_bounds__(256) void cvt_head(
    const float* __restrict__ w, unsigned short* __restrict__ hi,
    unsigned short* __restrict__ lo)
{
    int idx = blockIdx.x * 256 + threadIdx.x;   // 512*512
    int n = idx >> 9, k = idx & 511;
    float v = w[((size_t)(n >> 6) * 512 + k) * 64 + (n & 63)];
    unsigned short h = bfu(v);
    hi[idx] = h;
    lo[idx] = bfu(v - ubf(h));
}

// =================================================================
// bf16-split mma.sync GEMM: C = A[M,K] * W[N,K]^T (+bias/relu/res)
// CTA: 128x128 tile, 256 thr (8 warps, warp tile 64m x 32n).
// K chunked by 64; smem tiles [128][72] bf16 (144B stride, LDSM-clean).
// 3 terms (AhBh + AhBl + AlBh) into one fp32 accumulator.
// =================================================================
#define SREC 72
#define GEMM_SMEM (4 * 128 * SREC * 2)

__global__ __launch_bounds__(256) void gemm_mma(
    const unsigned short* __restrict__ Ah, const unsigned short* __restrict__ Al,
    const unsigned short* __restrict__ Bh, const unsigned short* __restrict__ Bl,
    const float* __restrict__ bias, const float* __restrict__ residual,
    float* __restrict__ C, int N, int K, int relu)
{
    extern __shared__ unsigned short smg[];
    unsigned short* sAh = smg;
    unsigned short* sAl = smg + 128 * SREC;
    unsigned short* sBh = smg + 2 * 128 * SREC;
    unsigned short* sBl = smg + 3 * 128 * SREC;
    const uint32_t sb = smem_u32(smg);

    const int tid = threadIdx.x;
    const int wid = tid >> 5, lane = tid & 31;
    const int m0 = blockIdx.x * 128, n0 = blockIdx.y * 128;
    const int wm = (wid & 1) * 64;       // warp m offset
    const int wn = (wid >> 1) * 32;      // warp n offset

    const int lr8 = lane & 7, lmt = lane >> 3;

    float acc[4][4][4] = {};             // [mtile16][ntile8][frag]

    const int lrow = tid >> 1;           // gmem/smem staging row
    const int lq   = (tid & 1) * 4;      // starting 8-elem quad

    for (int kc = 0; kc < K; kc += 64) {
        __syncthreads();
        #pragma unroll
        for (int i = 0; i < 4; i++) {
            int q = lq + i;
            int dst = lrow * SREC + q * 8;
            size_t gaoff = (size_t)(m0 + lrow) * K + kc + q * 8;
            size_t gboff = (size_t)(n0 + lrow) * K + kc + q * 8;
            *(uint4*)(sAh + dst) = *(const uint4*)(Ah + gaoff);
            *(uint4*)(sAl + dst) = *(const uint4*)(Al + gaoff);
            *(uint4*)(sBh + dst) = *(const uint4*)(Bh + gboff);
            *(uint4*)(sBl + dst) = *(const uint4*)(Bl + gboff);
        }
        __syncthreads();

        #pragma unroll
        for (int ks = 0; ks < 4; ks++) {
            const int k0 = ks * 16;
            // ---- B fragments: 4 ntiles of 8, loaded as 2 pairs ----
            uint32_t bh[4][2], bl[4][2];
            #pragma unroll
            for (int pr = 0; pr < 2; pr++) {
                // lane -> matrix mt: row = wn + pr*16 + (mt>>1)*8 + lr8,
                //                    col = k0 + (mt&1)*8
                uint32_t boff = (uint32_t)(wn + pr * 16 + (lmt >> 1) * 8 + lr8) * SREC
                              + k0 + (lmt & 1) * 8;
                uint32_t t[4];
                ldsm4(t, sb + 2 * (2 * 128 * SREC + boff));      // sBh
                bh[pr * 2 + 0][0] = t[0]; bh[pr * 2 + 0][1] = t[1];
                bh[pr * 2 + 1][0] = t[2]; bh[pr * 2 + 1][1] = t[3];
                ldsm4(t, sb + 2 * (3 * 128 * SREC + boff));      // sBl
                bl[pr * 2 + 0][0] = t[0]; bl[pr * 2 + 0][1] = t[1];
                bl[pr * 2 + 1][0] = t[2]; bl[pr * 2 + 1][1] = t[3];
            }
            // ---- A fragments + MMAs per 16-row mtile ----
            #pragma unroll
            for (int mi = 0; mi < 4; mi++) {
                // lane -> matrix mt: row = wm + mi*16 + (mt&1)*8 + lr8,
                //                    col = k0 + (mt>>1)*8   (a0,a1,a2,a3 order)
                uint32_t aoff = (uint32_t)(wm + mi * 16 + (lmt & 1) * 8 + lr8) * SREC
                              + k0 + (lmt >> 1) * 8;
                uint32_t ah4[4], al4[4];
                ldsm4(ah4, sb + 2 * aoff);                        // sAh
                ldsm4(al4, sb + 2 * (128 * SREC + aoff));         // sAl
                #pragma unroll
                for (int ni = 0; ni < 4; ni++) {
                    mma16816(acc[mi][ni], ah4, bh[ni]);
                    mma16816(acc[mi][ni], ah4, bl[ni]);
                    mma16816(acc[mi][ni], al4, bh[ni]);
                }
            }
        }
    }

    // ---- epilogue: frag (c0,c1)=row lane/4, cols 2*(lane%4); (c2,c3)=row+8
    #pragma unroll
    for (int mi = 0; mi < 4; mi++) {
        #pragma unroll
        for (int ni = 0; ni < 4; ni++) {
            int col = n0 + wn + ni * 8 + (lane & 3) * 2;
            int r0  = m0 + wm + mi * 16 + (lane >> 2);
            float bx = bias[col], by = bias[col + 1];
            float2 v0 = { acc[mi][ni][0] + bx, acc[mi][ni][1] + by };
            float2 v1 = { acc[mi][ni][2] + bx, acc[mi][ni][3] + by };
            if (relu) {
                v0.x = fmaxf(v0.x, 0.f); v0.y = fmaxf(v0.y, 0.f);
                v1.x = fmaxf(v1.x, 0.f); v1.y = fmaxf(v1.y, 0.f);
            }
            size_t i0 = (size_t)r0 * N + col;
            size_t i1 = (size_t)(r0 + 8) * N + col;
            if (residual) {
                float2 t0 = *(const float2*)(residual + i0);
                float2 t1 = *(const float2*)(residual + i1);
                v0.x += t0.x; v0.y += t0.y;
                v1.x += t1.x; v1.y += t1.y;
            }
            *(float2*)(C + i0) = v0;
            *(float2*)(C + i1) = v1;
        }
    }
}

// =================================================================
// Flash attention (unchanged, proven): block = (64 q-rows, h, b)
// =================================================================
#define AT_SMEM ((4 * 64 * 68 + 1024) * 4)

__global__ __launch_bounds__(256) void attn_kernel(
    const float* __restrict__ Q, const float* __restrict__ K,
    const float* __restrict__ V, const int* __restrict__ mask,
    float* __restrict__ O)
{
    const int qt = blockIdx.x;
    const int h  = blockIdx.y;
    const int b  = blockIdx.z;

    extern __shared__ float sm[];
    float* Qt  = sm;
    float* Kt  = sm + 64 * 68;
    float* Vs  = sm + 2 * 64 * 68;
    float* Pt  = sm + 3 * 64 * 68;
    float* msk = sm + 4 * 64 * 68;

    const int tid = threadIdx.x;
    const int tx = tid & 15, ty = tid >> 4;
    const float scale = 0.125f;

    #pragma unroll
    for (int it = 0; it < 4; it++) {
        int t = tid + it * 256;
        int r = t >> 4, d4 = (t & 15) * 4;
        float4 qv = *(const float4*)(Q + (size_t)(b * S_ + qt * 64 + r) * D_ + h * 64 + d4);
        Qt[(d4 + 0) * 68 + r] = qv.x; Qt[(d4 + 1) * 68 + r] = qv.y;
        Qt[(d4 + 2) * 68 + r] = qv.z; Qt[(d4 + 3) * 68 + r] = qv.w;
        msk[t] = (mask[b * S_ + t] != 0) ? 1.0f : 0.0f;
    }

    float acc[4][4] = {};
    float m_run[4], l_run[4];
    #pragma unroll
    for (int i = 0; i < 4; i++) { m_run[i] = -1e30f; l_run[i] = 0.0f; }

    for (int kc = 0; kc < 16; kc++) {
        __syncthreads();
        #pragma unroll
        for (int it = 0; it < 4; it++) {
            int t = tid + it * 256;
            int key = t >> 4, d4 = (t & 15) * 4;
            const float* base = K + (size_t)(b * S_ + kc * 64 + key) * D_ + h * 64;
            float4 kv = *(const float4*)(base + d4);
            Kt[(d4 + 0) * 68 + key] = kv.x; Kt[(d4 + 1) * 68 + key] = kv.y;
            Kt[(d4 + 2) * 68 + key] = kv.z; Kt[(d4 + 3) * 68 + key] = kv.w;
            float4 vv = *(const float4*)(V + (size_t)(b * S_ + kc * 64 + key) * D_ + h * 64 + d4);
            *(float4*)&Vs[key * 68 + d4] = vv;
        }
        __syncthreads();

        float s[4][4] = {};
        #pragma unroll 8
        for (int d = 0; d < 64; d++) {
            float4 q4 = *(const float4*)&Qt[d * 68 + ty * 4];
            float4 k4 = *(const float4*)&Kt[d * 68 + tx * 4];
            float qa[4] = {q4.x, q4.y, q4.z, q4.w};
            float ka[4] = {k4.x, k4.y, k4.z, k4.w};
            #pragma unroll
            for (int i = 0; i < 4; i++)
                #pragma unroll
                for (int j = 0; j < 4; j++)
                    s[i][j] += qa[i] * ka[j];
        }
        #pragma unroll
        for (int j = 0; j < 4; j++) {
            float mm = msk[kc * 64 + tx * 4 + j];
            #pragma unroll
            for (int i = 0; i < 4; i++)
                s[i][j] = (mm != 0.0f) ? s[i][j] * scale : -1e10f;
        }
        #pragma unroll
        for (int i = 0; i < 4; i++) {
            float mc = fmaxf(fmaxf(s[i][0], s[i][1]), fmaxf(s[i][2], s[i][3]));
            mc = fmaxf(mc, __shfl_xor_sync(0xffffffffu, mc, 1));
            mc = fmaxf(mc, __shfl_xor_sync(0xffffffffu, mc, 2));
            mc = fmaxf(mc, __shfl_xor_sync(0xffffffffu, mc, 4));
            mc = fmaxf(mc, __shfl_xor_sync(0xffffffffu, mc, 8));
            float mn = fmaxf(m_run[i], mc);
            float sc = __expf(m_run[i] - mn);
            m_run[i] = mn;
            float ls = 0.0f;
            #pragma unroll
            for (int j = 0; j < 4; j++) {
                float p = __expf(s[i][j] - mn);
                s[i][j] = p;
                ls += p;
            }
            ls += __shfl_xor_sync(0xffffffffu, ls, 1);
            ls += __shfl_xor_sync(0xffffffffu, ls, 2);
            ls += __shfl_xor_sync(0xffffffffu, ls, 4);
            ls += __shfl_xor_sync(0xffffffffu, ls, 8);
            l_run[i] = l_run[i] * sc + ls;
            #pragma unroll
            for (int j = 0; j < 4; j++) acc[i][j] *= sc;
        }
        #pragma unroll
        for (int j = 0; j < 4; j++)
            #pragma unroll
            for (int i = 0; i < 4; i++)
                Pt[(tx * 4 + j) * 68 + ty * 4 + i] = s[i][j];
        __syncthreads();
        #pragma unroll 8
        for (int k = 0; k < 64; k++) {
            float4 p4 = *(const float4*)&Pt[k * 68 + ty * 4];
            float4 v4 = *(const float4*)&Vs[k * 68 + tx * 4];
            float pa[4] = {p4.x, p4.y, p4.z, p4.w};
            float va[4] = {v4.x, v4.y, v4.z, v4.w};
            #pragma unroll
            for (int i = 0; i < 4; i++)
                #pragma unroll
                for (int j = 0; j < 4; j++)
                    acc[i][j] += pa[i] * va[j];
        }
    }

    #pragma unroll
    for (int i = 0; i < 4; i++) {
        float inv = 1.0f / l_run[i];
        float4 o;
        o.x = acc[i][0] * inv; o.y = acc[i][1] * inv;
        o.z = acc[i][2] * inv; o.w = acc[i][3] * inv;
        *(float4*)(O + (size_t)(b * S_ + qt * 64 + ty * 4 + i) * D_ + h * 64 + tx * 4) = o;
    }
}

// =================================================================
// LayerNorm (unchanged)
// =================================================================
__global__ __launch_bounds__(256) void ln_partial(const float* __restrict__ X,
                                                  float* __restrict__ part)
{
    const int b = blockIdx.x >> 4, seg = blockIdx.x & 15;
    const float4* x = (const float4*)(X + (size_t)b * S_ * D_ + seg * 32768);
    float s = 0.f, s2 = 0.f;
    #pragma unroll 4
    for (int i = threadIdx.x; i < 8192; i += 256) {
        float4 v = x[i];
        s  += v.x + v.y + v.z + v.w;
        s2 += v.x * v.x + v.y * v.y + v.z * v.z + v.w * v.w;
    }
    #pragma unroll
    for (int o = 16; o; o >>= 1) {
        s  += __shfl_xor_sync(0xffffffffu, s, o);
        s2 += __shfl_xor_sync(0xffffffffu, s2, o);
    }
    __shared__ float ws[8], ws2[8];
    int lane = threadIdx.x & 31, wp = threadIdx.x >> 5;
    if (lane == 0) { ws[wp] = s; ws2[wp] = s2; }
    __syncthreads();
    if (threadIdx.x == 0) {
        float a = 0.f, a2 = 0.f;
        #pragma unroll
        for (int w = 0; w < 8; w++) { a += ws[w]; a2 += ws2[w]; }
        part[blockIdx.x * 2 + 0] = a;
        part[blockIdx.x * 2 + 1] = a2;
    }
}

__global__ void ln_finalize(const float* __restrict__ part, float* __restrict__ stats)
{
    int b = threadIdx.x;
    if (b < B_) {
        float s = 0.f, s2 = 0.f;
        for (int k = 0; k < 16; k++) {
            s  += part[(b * 16 + k) * 2 + 0];
            s2 += part[(b * 16 + k) * 2 + 1];
        }
        const float inv_n = 1.0f / (float)(S_ * D_);
        float mean = s * inv_n;
        float var  = s2 * inv_n - mean * mean;
        stats[b * 2 + 0] = mean;
        stats[b * 2 + 1] = rsqrtf(var + 1e-6f);
    }
}

__global__ __launch_bounds__(256) void ln_apply(
    const float* __restrict__ X, const float* __restrict__ w,
    const float* __restrict__ bias, const float* __restrict__ stats,
    float* __restrict__ Out)
{
    int i = blockIdx.x * 256 + threadIdx.x;
    int b  = i >> 17;
    int sd = i - (b << 17);
    float mean = stats[b * 2], rstd = stats[b * 2 + 1];
    float4 xv = ((const float4*)X)[i];
    float4 wv = ((const float4*)w)[sd];
    float4 bv = ((const float4*)bias)[sd];
    float4 o;
    o.x = (xv.x - mean) * rstd * wv.x + bv.x;
    o.y = (xv.y - mean) * rstd * wv.y + bv.y;
    o.z = (xv.z - mean) * rstd * wv.z + bv.z;
    o.w = (xv.w - mean) * rstd * wv.w + bv.w;
    ((float4*)Out)[i] = o;
}

// =================================================================
extern "C" void kernel_launch(void* const* d_in, const int* in_sizes, int n_in,
                              void* d_out, int out_size)
{
    const float* x        = (const float*)d_in[0];
    const float* y        = (const float*)d_in[1];
    const int*   src_mask = (const int*)  d_in[2];
    const int*   trg_mask = (const int*)  d_in[3];
    const float* m1_wq = (const float*)d_in[4];
    const float* m1_bq = (const float*)d_in[5];
    const float* m1_wk = (const float*)d_in[6];
    const float* m1_bk = (const float*)d_in[7];
    const float* m1_wv = (const float*)d_in[8];
    const float* m1_bv = (const float*)d_in[9];
    const float* m1_wo = (const float*)d_in[10];
    const float* m1_bo = (const float*)d_in[11];
    const float* m2_wq = (const float*)d_in[12];
    const float* m2_bq = (const float*)d_in[13];
    const float* m2_wk = (const float*)d_in[14];
    const float* m2_bk = (const float*)d_in[15];
    const float* m2_wv = (const float*)d_in[16];
    const float* m2_bv = (const float*)d_in[17];
    const float* m2_wo = (const float*)d_in[18];
    const float* m2_bo = (const float*)d_in[19];
    const float* pw1   = (const float*)d_in[20];
    const float* pb1   = (const float*)d_in[21];
    const float* pw2   = (const float*)d_in[22];
    const float* pb2   = (const float*)d_in[23];
    const float* ln1_w = (const float*)d_in[24];
    const float* ln1_b = (const float*)d_in[25];
    const float* ln2_w = (const float*)d_in[26];
    const float* ln2_b = (const float*)d_in[27];
    const float* ln3_w = (const float*)d_in[28];
    const float* ln3_b = (const float*)d_in[29];
    float* out = (float*)d_out;

    float *q, *k, *v, *attn, *res, *x1, *x2, *ff, *part, *stats;
    unsigned short *ah, *al, *wh, *wl;
    cudaGetSymbolAddress((void**)&q,     g_q);
    cudaGetSymbolAddress((void**)&k,     g_k);
    cudaGetSymbolAddress((void**)&v,     g_v);
    cudaGetSymbolAddress((void**)&attn,  g_attn);
    cudaGetSymbolAddress((void**)&res,   g_res);
    cudaGetSymbolAddress((void**)&x1,    g_x1);
    cudaGetSymbolAddress((void**)&x2,    g_x2);
    cudaGetSymbolAddress((void**)&ff,    g_ff);
    cudaGetSymbolAddress((void**)&part,  g_part);
    cudaGetSymbolAddress((void**)&stats, g_stats);
    cudaGetSymbolAddress((void**)&ah,    g_ah);
    cudaGetSymbolAddress((void**)&al,    g_al);
    cudaGetSymbolAddress((void**)&wh,    g_wh);
    cudaGetSymbolAddress((void**)&wl,    g_wl);

    cudaFuncSetAttribute(attn_kernel,
                         cudaFuncAttributeMaxDynamicSharedMemorySize, AT_SMEM);
    cudaFuncSetAttribute(gemm_mma,
                         cudaFuncAttributeMaxDynamicSharedMemorySize, GEMM_SMEM);

    const dim3 gAttn(S_ / 64, H_, B_);
    const int  gApply = (BS_ * D_ / 4) / 256;
    const int  nActD  = BS_ * D_ / 4;
    const int  nActFF = BS_ * DFF_ / 4;
    const int  nW512  = D_ * D_ / 4;
    const int  nWff   = DFF_ * D_ / 4;
    const dim3 gG512(BS_ / 128, D_ / 128);
    const dim3 gGff1(BS_ / 128, DFF_ / 128);
    const int  cvB = 256;

    #define GEMM(AH, AL, BIAS, RES, OUT, N, K, RELU, GRID) \
        gemm_mma<<<GRID, 256, GEMM_SMEM>>>(AH, AL, wh, wl, BIAS, RES, OUT, N, K, RELU)

    // ---- self-attention ----
    cvt_split<<<(nActD + cvB - 1) / cvB, cvB>>>(x, ah, al, nActD);
    cvt_head<<<(D_ * D_) / cvB, cvB>>>(m1_wq, wh, wl);
    GEMM(ah, al, m1_bq, nullptr, q, D_, D_, 0, gG512);
    cvt_head<<<(D_ * D_) / cvB, cvB>>>(m1_wk, wh, wl);
    GEMM(ah, al, m1_bk, nullptr, k, D_, D_, 0, gG512);
    cvt_head<<<(D_ * D_) / cvB, cvB>>>(m1_wv, wh, wl);
    GEMM(ah, al, m1_bv, nullptr, v, D_, D_, 0, gG512);
    attn_kernel<<<gAttn, 256, AT_SMEM>>>(q, k, v, trg_mask, attn);
    cvt_split<<<(nActD + cvB - 1) / cvB, cvB>>>(attn, ah, al, nActD);
    cvt_split<<<(nW512 + cvB - 1) / cvB, cvB>>>(m1_wo, wh, wl, nW512);
    GEMM(ah, al, m1_bo, x, res, D_, D_, 0, gG512);
    ln_partial<<<16 * B_, 256>>>(res, part);
    ln_finalize<<<1, 32>>>(part, stats);
    ln_apply<<<gApply, 256>>>(res, ln1_w, ln1_b, stats, x1);

    // ---- cross-attention ----
    cvt_split<<<(nActD + cvB - 1) / cvB, cvB>>>(x1, ah, al, nActD);
    cvt_head<<<(D_ * D_) / cvB, cvB>>>(m2_wq, wh, wl);
    GEMM(ah, al, m2_bq, nullptr, q, D_, D_, 0, gG512);
    cvt_split<<<(nActD + cvB - 1) / cvB, cvB>>>(y, ah, al, nActD);
    cvt_head<<<(D_ * D_) / cvB, cvB>>>(m2_wk, wh, wl);
    GEMM(ah, al, m2_bk, nullptr, k, D_, D_, 0, gG512);
    cvt_head<<<(D_ * D_) / cvB, cvB>>>(m2_wv, wh, wl);
    GEMM(ah, al, m2_bv, nullptr, v, D_, D_, 0, gG512);
    attn_kernel<<<gAttn, 256, AT_SMEM>>>(q, k, v, src_mask, attn);
    cvt_split<<<(nActD + cvB - 1) / cvB, cvB>>>(attn, ah, al, nActD);
    cvt_split<<<(nW512 + cvB - 1) / cvB, cvB>>>(m2_wo, wh, wl, nW512);
    GEMM(ah, al, m2_bo, x1, res, D_, D_, 0, gG512);
    ln_partial<<<16 * B_, 256>>>(res, part);
    ln_finalize<<<1, 32>>>(part, stats);
    ln_apply<<<gApply, 256>>>(res, ln2_w, ln2_b, stats, x2);

    // ---- FFN ----
    cvt_split<<<(nActD + cvB - 1) / cvB, cvB>>>(x2, ah, al, nActD);
    cvt_split<<<(nWff + cvB - 1) / cvB, cvB>>>(pw1, wh, wl, nWff);
    GEMM(ah, al, pb1, nullptr, ff, DFF_, D_, 1, gGff1);
    cvt_split<<<(nActFF + cvB - 1) / cvB, cvB>>>(ff, ah, al, nActFF);
    cvt_split<<<(nWff + cvB - 1) / cvB, cvB>>>(pw2, wh, wl, nWff);
    GEMM(ah, al, pb2, x2, res, D_, DFF_, 0, gG512);
    ln_partial<<<16 * B_, 256>>>(res, part);
    ln_finalize<<<1, 32>>>(part, stats);
    ln_apply<<<gApply, 256>>>(res, ln3_w, ln3_b, stats, out);

    #undef GEMM
}

// round 12
// speedup vs baseline: 2.8221x; 1.0114x over previous
#include <cuda_runtime.h>
#include <cuda_bf16.h>
#include <cstdint>

#define B_   8
#define S_   1024
#define D_   512
#define H_   8
#define DFF_ 2048
#define BS_  (B_ * S_)

// ---------------- scratch (no allocations allowed) ----------------
__device__ float g_q[BS_ * D_];
__device__ float g_k[BS_ * D_];
__device__ float g_v[BS_ * D_];
__device__ float g_res[BS_ * D_];
__device__ float g_x1[BS_ * D_];
__device__ float g_x2[BS_ * D_];
__device__ float g_ff[BS_ * DFF_];
__device__ float g_part[256];
__device__ float g_stats[2 * B_];
// bf16 split operand buffers
__device__ unsigned short g_ah[BS_ * DFF_];   // activation hi
__device__ unsigned short g_al[BS_ * DFF_];   // activation lo
__device__ unsigned short g_wh[DFF_ * D_];    // weight hi
__device__ unsigned short g_wl[DFF_ * D_];    // weight lo

// ---------------- helpers ----------------
static __device__ __forceinline__ unsigned short bfu(float x) {
    __nv_bfloat16 h = __float2bfloat16(x);
    return *reinterpret_cast<unsigned short*>(&h);
}
static __device__ __forceinline__ float ubf(unsigned short u) {
    __nv_bfloat16 h = *reinterpret_cast<__nv_bfloat16*>(&u);
    return __bfloat162float(h);
}
static __device__ __forceinline__ uint32_t smem_u32(const void* p) {
    uint32_t a;
    asm("{ .reg .u64 t; cvta.to.shared.u64 t, %1; cvt.u32.u64 %0, t; }"
        : "=r"(a) : "l"(p));
    return a;
}
static __device__ __forceinline__ void ldsm4(uint32_t* r, uint32_t addr) {
    asm volatile("ldmatrix.sync.aligned.m8n8.x4.shared.b16 {%0,%1,%2,%3}, [%4];"
        : "=r"(r[0]), "=r"(r[1]), "=r"(r[2]), "=r"(r[3]) : "r"(addr));
}
static __device__ __forceinline__ void ldsm4t(uint32_t* r, uint32_t addr) {
    asm volatile("ldmatrix.sync.aligned.m8n8.x4.trans.shared.b16 {%0,%1,%2,%3}, [%4];"
        : "=r"(r[0]), "=r"(r[1]), "=r"(r[2]), "=r"(r[3]) : "r"(addr));
}
static __device__ __forceinline__ void mma16816(
    float* c, const uint32_t* a, const uint32_t* b)
{
    asm volatile(
        "mma.sync.aligned.m16n8k16.row.col.f32.bf16.bf16.f32 "
        "{%0,%1,%2,%3}, {%4,%5,%6,%7}, {%8,%9}, {%0,%1,%2,%3};"
        : "+f"(c[0]), "+f"(c[1]), "+f"(c[2]), "+f"(c[3])
        : "r"(a[0]), "r"(a[1]), "r"(a[2]), "r"(a[3]), "r"(b[0]), "r"(b[1]));
}
// split two fp32 into packed bf16x2 hi & lo-residual words ({lo half = first})
static __device__ __forceinline__ void sp2(float v0, float v1,
                                           uint32_t& h2, uint32_t& l2)
{
    unsigned short h0 = bfu(v0), h1 = bfu(v1);
    unsigned short l0 = bfu(v0 - ubf(h0)), l1 = bfu(v1 - ubf(h1));
    h2 = (uint32_t)h0 | ((uint32_t)h1 << 16);
    l2 = (uint32_t)l0 | ((uint32_t)l1 << 16);
}

// =================================================================
// Operand conversion: fp32 -> bf16 hi + bf16 lo
// =================================================================
__global__ __launch_bounds__(256) void cvt_split(
    const float* __restrict__ in, unsigned short* __restrict__ hi,
    unsigned short* __restrict__ lo, int n4)
{
    int i = blockIdx.x * 256 + threadIdx.x;
    if (i >= n4) return;
    float4 v = ((const float4*)in)[i];
    ushort4 H, L;
    H.x = bfu(v.x); L.x = bfu(v.x - ubf(H.x));
    H.y = bfu(v.y); L.y = bfu(v.y - ubf(H.y));
    H.z = bfu(v.z); L.z = bfu(v.z - ubf(H.z));
    H.w = bfu(v.w); L.w = bfu(v.w - ubf(H.w));
    ((ushort4*)hi)[i] = H;
    ((ushort4*)lo)[i] = L;
}

// Head weights [H, D, 64] -> trans-B layout [N=512, K=512] hi/lo
__global__ __launch_bounds__(256) void cvt_head(
    const float* __restrict__ w, unsigned short* __restrict__ hi,
    unsigned short* __restrict__ lo)
{
    int idx = blockIdx.x * 256 + threadIdx.x;
    int n = idx >> 9, k = idx & 511;
    float v = w[((size_t)(n >> 6) * 512 + k) * 64 + (n & 63)];
    unsigned short h = bfu(v);
    hi[idx] = h;
    lo[idx] = bfu(v - ubf(h));
}

// =================================================================
// bf16-split mma.sync GEMM (proven round 8, unchanged)
// =================================================================
#define SREC 72
#define GEMM_SMEM (4 * 128 * SREC * 2)

__global__ __launch_bounds__(256) void gemm_mma(
    const unsigned short* __restrict__ Ah, const unsigned short* __restrict__ Al,
    const unsigned short* __restrict__ Bh, const unsigned short* __restrict__ Bl,
    const float* __restrict__ bias, const float* __restrict__ residual,
    float* __restrict__ C, int N, int K, int relu)
{
    extern __shared__ unsigned short smg[];
    unsigned short* sAh = smg;
    unsigned short* sAl = smg + 128 * SREC;
    unsigned short* sBh = smg + 2 * 128 * SREC;
    unsigned short* sBl = smg + 3 * 128 * SREC;
    const uint32_t sb = smem_u32(smg);

    const int tid = threadIdx.x;
    const int wid = tid >> 5, lane = tid & 31;
    const int m0 = blockIdx.x * 128, n0 = blockIdx.y * 128;
    const int wm = (wid & 1) * 64;
    const int wn = (wid >> 1) * 32;
    const int lr8 = lane & 7, lmt = lane >> 3;

    float acc[4][4][4] = {};

    const int lrow = tid >> 1;
    const int lq   = (tid & 1) * 4;

    for (int kc = 0; kc < K; kc += 64) {
        __syncthreads();
        #pragma unroll
        for (int i = 0; i < 4; i++) {
            int q = lq + i;
            int dst = lrow * SREC + q * 8;
            size_t gaoff = (size_t)(m0 + lrow) * K + kc + q * 8;
            size_t gboff = (size_t)(n0 + lrow) * K + kc + q * 8;
            *(uint4*)(sAh + dst) = *(const uint4*)(Ah + gaoff);
            *(uint4*)(sAl + dst) = *(const uint4*)(Al + gaoff);
            *(uint4*)(sBh + dst) = *(const uint4*)(Bh + gboff);
            *(uint4*)(sBl + dst) = *(const uint4*)(Bl + gboff);
        }
        __syncthreads();

        #pragma unroll
        for (int ks = 0; ks < 4; ks++) {
            const int k0 = ks * 16;
            uint32_t bh[4][2], bl[4][2];
            #pragma unroll
            for (int pr = 0; pr < 2; pr++) {
                uint32_t boff = (uint32_t)(wn + pr * 16 + (lmt >> 1) * 8 + lr8) * SREC
                              + k0 + (lmt & 1) * 8;
                uint32_t t[4];
                ldsm4(t, sb + 2 * (2 * 128 * SREC + boff));
                bh[pr * 2 + 0][0] = t[0]; bh[pr * 2 + 0][1] = t[1];
                bh[pr * 2 + 1][0] = t[2]; bh[pr * 2 + 1][1] = t[3];
                ldsm4(t, sb + 2 * (3 * 128 * SREC + boff));
                bl[pr * 2 + 0][0] = t[0]; bl[pr * 2 + 0][1] = t[1];
                bl[pr * 2 + 1][0] = t[2]; bl[pr * 2 + 1][1] = t[3];
            }
            #pragma unroll
            for (int mi = 0; mi < 4; mi++) {
                uint32_t aoff = (uint32_t)(wm + mi * 16 + (lmt & 1) * 8 + lr8) * SREC
                              + k0 + (lmt >> 1) * 8;
                uint32_t ah4[4], al4[4];
                ldsm4(ah4, sb + 2 * aoff);
                ldsm4(al4, sb + 2 * (128 * SREC + aoff));
                #pragma unroll
                for (int ni = 0; ni < 4; ni++) {
                    mma16816(acc[mi][ni], ah4, bh[ni]);
                    mma16816(acc[mi][ni], ah4, bl[ni]);
                    mma16816(acc[mi][ni], al4, bh[ni]);
                }
            }
        }
    }

    #pragma unroll
    for (int mi = 0; mi < 4; mi++) {
        #pragma unroll
        for (int ni = 0; ni < 4; ni++) {
            int col = n0 + wn + ni * 8 + (lane & 3) * 2;
            int r0  = m0 + wm + mi * 16 + (lane >> 2);
            float bx = bias[col], by = bias[col + 1];
            float2 v0 = { acc[mi][ni][0] + bx, acc[mi][ni][1] + by };
            float2 v1 = { acc[mi][ni][2] + bx, acc[mi][ni][3] + by };
            if (relu) {
                v0.x = fmaxf(v0.x, 0.f); v0.y = fmaxf(v0.y, 0.f);
                v1.x = fmaxf(v1.x, 0.f); v1.y = fmaxf(v1.y, 0.f);
            }
            size_t i0 = (size_t)r0 * N + col;
            size_t i1 = (size_t)(r0 + 8) * N + col;
            if (residual) {
                float2 t0 = *(const float2*)(residual + i0);
                float2 t1 = *(const float2*)(residual + i1);
                v0.x += t0.x; v0.y += t0.y;
                v1.x += t1.x; v1.y += t1.y;
            }
            *(float2*)(C + i0) = v0;
            *(float2*)(C + i1) = v1;
        }
    }
}

// =================================================================
// Flash attention on tensor cores, bf16-split, fragment softmax.
// Block = (128 q-rows, h, b); 8 warps x 16 rows. K/V chunks of 64.
// Output written directly as bf16 hi/lo GEMM operands.
// smem (ushort idx): Qh 0, Ql 9216, Kh 18432, Kl 23040,
//                    Vh 27648, Vl 32256; mask fp32 @ byte 73728.
// =================================================================
#define AT2_SMEM 77824

__global__ __launch_bounds__(256, 2) void attn_mma(
    const float* __restrict__ Q, const float* __restrict__ K,
    const float* __restrict__ V, const int* __restrict__ mask,
    unsigned short* __restrict__ Oh, unsigned short* __restrict__ Ol)
{
    const int qt = blockIdx.x, h = blockIdx.y, b = blockIdx.z;
    extern __shared__ unsigned short sma[];
    const uint32_t sb = smem_u32(sma);
    unsigned short* sQh = sma;
    unsigned short* sQl = sma + 9216;
    unsigned short* sKh = sma + 18432;
    unsigned short* sKl = sma + 23040;
    unsigned short* sVh = sma + 27648;
    unsigned short* sVl = sma + 32256;
    float* msk = (float*)(sma + 36864);

    const int tid = threadIdx.x, wid = tid >> 5, lane = tid & 31;
    const int wm = wid * 16;
    const int lr8 = lane & 7, lmt = lane >> 3;

    // ---- Q load (pre-scaled by 1/8 — exact) + split; mask flags ----
    #pragma unroll
    for (int it = 0; it < 8; it++) {
        int t = tid + it * 256;
        int row = t >> 4, c4 = (t & 15) * 4;
        float4 qv = *(const float4*)(Q + (size_t)(b * S_ + qt * 128 + row) * D_
                                       + h * 64 + c4);
        qv.x *= 0.125f; qv.y *= 0.125f; qv.z *= 0.125f; qv.w *= 0.125f;
        ushort4 hh, ll;
        hh.x = bfu(qv.x); ll.x = bfu(qv.x - ubf(hh.x));
        hh.y = bfu(qv.y); ll.y = bfu(qv.y - ubf(hh.y));
        hh.z = bfu(qv.z); ll.z = bfu(qv.z - ubf(hh.z));
        hh.w = bfu(qv.w); ll.w = bfu(qv.w - ubf(hh.w));
        *(ushort4*)(sQh + row * 72 + c4) = hh;
        *(ushort4*)(sQl + row * 72 + c4) = ll;
    }
    #pragma unroll
    for (int it = 0; it < 4; it++) {
        int t = tid + it * 256;
        msk[t] = (mask[b * S_ + t] != 0) ? 1.0f : 0.0f;
    }

    float acc[8][4] = {};
    float m_run[2] = {-1e30f, -1e30f}, l_run[2] = {0.f, 0.f};

    for (int kc = 0; kc < 16; kc++) {
        __syncthreads();
        // ---- K/V chunk load + split ----
        #pragma unroll
        for (int it = 0; it < 4; it++) {
            int t = tid + it * 256;
            int row = t >> 4, c4 = (t & 15) * 4;
            size_t goff = (size_t)(b * S_ + kc * 64 + row) * D_ + h * 64 + c4;
            float4 kv = *(const float4*)(K + goff);
            ushort4 hh, ll;
            hh.x = bfu(kv.x); ll.x = bfu(kv.x - ubf(hh.x));
            hh.y = bfu(kv.y); ll.y = bfu(kv.y - ubf(hh.y));
            hh.z = bfu(kv.z); ll.z = bfu(kv.z - ubf(hh.z));
            hh.w = bfu(kv.w); ll.w = bfu(kv.w - ubf(hh.w));
            *(ushort4*)(sKh + row * 72 + c4) = hh;
            *(ushort4*)(sKl + row * 72 + c4) = ll;
            float4 vv = *(const float4*)(V + goff);
            hh.x = bfu(vv.x); ll.x = bfu(vv.x - ubf(hh.x));
            hh.y = bfu(vv.y); ll.y = bfu(vv.y - ubf(hh.y));
            hh.z = bfu(vv.z); ll.z = bfu(vv.z - ubf(hh.z));
            hh.w = bfu(vv.w); ll.w = bfu(vv.w - ubf(hh.w));
            *(ushort4*)(sVh + row * 72 + c4) = hh;
            *(ushort4*)(sVl + row * 72 + c4) = ll;
        }
        __syncthreads();

        // ---- scores: S = Q K^T (3 split terms) ----
        float s[8][4] = {};
        #pragma unroll
        for (int ks = 0; ks < 4; ks++) {
            uint32_t qh4[4], ql4[4];
            uint32_t aoff = (uint32_t)(wm + (lmt & 1) * 8 + lr8) * 72
                          + ks * 16 + (lmt >> 1) * 8;
            ldsm4(qh4, sb + 2 * aoff);
            ldsm4(ql4, sb + 2 * (9216 + aoff));
            #pragma unroll
            for (int pr = 0; pr < 4; pr++) {
                uint32_t boff = (uint32_t)(pr * 16 + (lmt >> 1) * 8 + lr8) * 72
                              + ks * 16 + (lmt & 1) * 8;
                uint32_t th[4], tl[4];
                ldsm4(th, sb + 2 * (18432 + boff));
                ldsm4(tl, sb + 2 * (23040 + boff));
                uint32_t bh0[2] = {th[0], th[1]}, bh1[2] = {th[2], th[3]};
                uint32_t bl0[2] = {tl[0], tl[1]}, bl1[2] = {tl[2], tl[3]};
                mma16816(s[2 * pr],     qh4, bh0);
                mma16816(s[2 * pr],     qh4, bl0);
                mma16816(s[2 * pr],     ql4, bh0);
                mma16816(s[2 * pr + 1], qh4, bh1);
                mma16816(s[2 * pr + 1], qh4, bl1);
                mma16816(s[2 * pr + 1], ql4, bh1);
            }
        }

        // ---- mask ----
        #pragma unroll
        for (int nt = 0; nt < 8; nt++) {
            int colb = kc * 64 + nt * 8 + 2 * (lane & 3);
            float m0 = msk[colb], m1 = msk[colb + 1];
            if (m0 == 0.f) { s[nt][0] = -1e10f; s[nt][2] = -1e10f; }
            if (m1 == 0.f) { s[nt][1] = -1e10f; s[nt][3] = -1e10f; }
        }

        // ---- online softmax (rows r0 = lane>>2, r1 = r0+8) ----
        float mc0 = -1e30f, mc1 = -1e30f;
        #pragma unroll
        for (int nt = 0; nt < 8; nt++) {
            mc0 = fmaxf(mc0, fmaxf(s[nt][0], s[nt][1]));
            mc1 = fmaxf(mc1, fmaxf(s[nt][2], s[nt][3]));
        }
        mc0 = fmaxf(mc0, __shfl_xor_sync(0xffffffffu, mc0, 1));
        mc0 = fmaxf(mc0, __shfl_xor_sync(0xffffffffu, mc0, 2));
        mc1 = fmaxf(mc1, __shfl_xor_sync(0xffffffffu, mc1, 1));
        mc1 = fmaxf(mc1, __shfl_xor_sync(0xffffffffu, mc1, 2));
        float mn0 = fmaxf(m_run[0], mc0), mn1 = fmaxf(m_run[1], mc1);
        float sc0 = __expf(m_run[0] - mn0), sc1 = __expf(m_run[1] - mn1);
        m_run[0] = mn0; m_run[1] = mn1;
        float ls0 = 0.f, ls1 = 0.f;
        #pragma unroll
        for (int nt = 0; nt < 8; nt++) {
            s[nt][0] = __expf(s[nt][0] - mn0); ls0 += s[nt][0];
            s[nt][1] = __expf(s[nt][1] - mn0); ls0 += s[nt][1];
            s[nt][2] = __expf(s[nt][2] - mn1); ls1 += s[nt][2];
            s[nt][3] = __expf(s[nt][3] - mn1); ls1 += s[nt][3];
        }
        ls0 += __shfl_xor_sync(0xffffffffu, ls0, 1);
        ls0 += __shfl_xor_sync(0xffffffffu, ls0, 2);
        ls1 += __shfl_xor_sync(0xffffffffu, ls1, 1);
        ls1 += __shfl_xor_sync(0xffffffffu, ls1, 2);
        l_run[0] = l_run[0] * sc0 + ls0;
        l_run[1] = l_run[1] * sc1 + ls1;
        #pragma unroll
        for (int nt = 0; nt < 8; nt++) {
            acc[nt][0] *= sc0; acc[nt][1] *= sc0;
            acc[nt][2] *= sc1; acc[nt][3] *= sc1;
        }

        // ---- O += P V (P from fragments, 3 split terms) ----
        #pragma unroll
        for (int ks = 0; ks < 4; ks++) {
            uint32_t aP[4], aL[4];
            sp2(s[2 * ks][0],     s[2 * ks][1],     aP[0], aL[0]);
            sp2(s[2 * ks][2],     s[2 * ks][3],     aP[1], aL[1]);
            sp2(s[2 * ks + 1][0], s[2 * ks + 1][1], aP[2], aL[2]);
            sp2(s[2 * ks + 1][2], s[2 * ks + 1][3], aP[3], aL[3]);
            #pragma unroll
            for (int pr = 0; pr < 4; pr++) {
                uint32_t boff = (uint32_t)(ks * 16 + (lmt & 1) * 8 + lr8) * 72
                              + pr * 16 + (lmt >> 1) * 8;
                uint32_t th[4], tl[4];
                ldsm4t(th, sb + 2 * (27648 + boff));
                ldsm4t(tl, sb + 2 * (32256 + boff));
                uint32_t bh0[2] = {th[0], th[1]}, bh1[2] = {th[2], th[3]};
                uint32_t bl0[2] = {tl[0], tl[1]}, bl1[2] = {tl[2], tl[3]};
                mma16816(acc[2 * pr],     aP, bh0);
                mma16816(acc[2 * pr],     aP, bl0);
                mma16816(acc[2 * pr],     aL, bh0);
                mma16816(acc[2 * pr + 1], aP, bh1);
                mma16816(acc[2 * pr + 1], aP, bl1);
                mma16816(acc[2 * pr + 1], aL, bh1);
            }
        }
    }

    // ---- output: normalize, split to bf16 hi/lo operand buffers ----
    float inv0 = 1.0f / l_run[0], inv1 = 1.0f / l_run[1];
    size_t row0 = (size_t)(b * S_ + qt * 128 + wm + (lane >> 2));
    #pragma unroll
    for (int nt = 0; nt < 8; nt++) {
        int col = h * 64 + nt * 8 + 2 * (lane & 3);
        uint32_t h2, l2;
        sp2(acc[nt][0] * inv0, acc[nt][1] * inv0, h2, l2);
        *(uint32_t*)(Oh + row0 * D_ + col) = h2;
        *(uint32_t*)(Ol + row0 * D_ + col) = l2;
        sp2(acc[nt][2] * inv1, acc[nt][3] * inv1, h2, l2);
        *(uint32_t*)(Oh + (row0 + 8) * D_ + col) = h2;
        *(uint32_t*)(Ol + (row0 + 8) * D_ + col) = l2;
    }
}

// =================================================================
// LayerNorm (unchanged)
// =================================================================
__global__ __launch_bounds__(256) void ln_partial(const float* __restrict__ X,
                                                  float* __restrict__ part)
{
    const int b = blockIdx.x >> 4, seg = blockIdx.x & 15;
    const float4* x = (const float4*)(X + (size_t)b * S_ * D_ + seg * 32768);
    float s = 0.f, s2 = 0.f;
    #pragma unroll 4
    for (int i = threadIdx.x; i < 8192; i += 256) {
        float4 v = x[i];
        s  += v.x + v.y + v.z + v.w;
        s2 += v.x * v.x + v.y * v.y + v.z * v.z + v.w * v.w;
    }
    #pragma unroll
    for (int o = 16; o; o >>= 1) {
        s  += __shfl_xor_sync(0xffffffffu, s, o);
        s2 += __shfl_xor_sync(0xffffffffu, s2, o);
    }
    __shared__ float ws[8], ws2[8];
    int lane = threadIdx.x & 31, wp = threadIdx.x >> 5;
    if (lane == 0) { ws[wp] = s; ws2[wp] = s2; }
    __syncthreads();
    if (threadIdx.x == 0) {
        float a = 0.f, a2 = 0.f;
        #pragma unroll
        for (int w = 0; w < 8; w++) { a += ws[w]; a2 += ws2[w]; }
        part[blockIdx.x * 2 + 0] = a;
        part[blockIdx.x * 2 + 1] = a2;
    }
}

__global__ void ln_finalize(const float* __restrict__ part, float* __restrict__ stats)
{
    int b = threadIdx.x;
    if (b < B_) {
        float s = 0.f, s2 = 0.f;
        for (int k = 0; k < 16; k++) {
            s  += part[(b * 16 + k) * 2 + 0];
            s2 += part[(b * 16 + k) * 2 + 1];
        }
        const float inv_n = 1.0f / (float)(S_ * D_);
        float mean = s * inv_n;
        float var  = s2 * inv_n - mean * mean;
        stats[b * 2 + 0] = mean;
        stats[b * 2 + 1] = rsqrtf(var + 1e-6f);
    }
}

__global__ __launch_bounds__(256) void ln_apply(
    const float* __restrict__ X, const float* __restrict__ w,
    const float* __restrict__ bias, const float* __restrict__ stats,
    float* __restrict__ Out)
{
    int i = blockIdx.x * 256 + threadIdx.x;
    int b  = i >> 17;
    int sd = i - (b << 17);
    float mean = stats[b * 2], rstd = stats[b * 2 + 1];
    float4 xv = ((const float4*)X)[i];
    float4 wv = ((const float4*)w)[sd];
    float4 bv = ((const float4*)bias)[sd];
    float4 o;
    o.x = (xv.x - mean) * rstd * wv.x + bv.x;
    o.y = (xv.y - mean) * rstd * wv.y + bv.y;
    o.z = (xv.z - mean) * rstd * wv.z + bv.z;
    o.w = (xv.w - mean) * rstd * wv.w + bv.w;
    ((float4*)Out)[i] = o;
}

// =================================================================
extern "C" void kernel_launch(void* const* d_in, const int* in_sizes, int n_in,
                              void* d_out, int out_size)
{
    const float* x        = (const float*)d_in[0];
    const float* y        = (const float*)d_in[1];
    const int*   src_mask = (const int*)  d_in[2];
    const int*   trg_mask = (const int*)  d_in[3];
    const float* m1_wq = (const float*)d_in[4];
    const float* m1_bq = (const float*)d_in[5];
    const float* m1_wk = (const float*)d_in[6];
    const float* m1_bk = (const float*)d_in[7];
    const float* m1_wv = (const float*)d_in[8];
    const float* m1_bv = (const float*)d_in[9];
    const float* m1_wo = (const float*)d_in[10];
    const float* m1_bo = (const float*)d_in[11];
    const float* m2_wq = (const float*)d_in[12];
    const float* m2_bq = (const float*)d_in[13];
    const float* m2_wk = (const float*)d_in[14];
    const float* m2_bk = (const float*)d_in[15];
    const float* m2_wv = (const float*)d_in[16];
    const float* m2_bv = (const float*)d_in[17];
    const float* m2_wo = (const float*)d_in[18];
    const float* m2_bo = (const float*)d_in[19];
    const float* pw1   = (const float*)d_in[20];
    const float* pb1   = (const float*)d_in[21];
    const float* pw2   = (const float*)d_in[22];
    const float* pb2   = (const float*)d_in[23];
    const float* ln1_w = (const float*)d_in[24];
    const float* ln1_b = (const float*)d_in[25];
    const float* ln2_w = (const float*)d_in[26];
    const float* ln2_b = (const float*)d_in[27];
    const float* ln3_w = (const float*)d_in[28];
    const float* ln3_b = (const float*)d_in[29];
    float* out = (float*)d_out;

    float *q, *k, *v, *res, *x1, *x2, *ff, *part, *stats;
    unsigned short *ah, *al, *wh, *wl;
    cudaGetSymbolAddress((void**)&q,     g_q);
    cudaGetSymbolAddress((void**)&k,     g_k);
    cudaGetSymbolAddress((void**)&v,     g_v);
    cudaGetSymbolAddress((void**)&res,   g_res);
    cudaGetSymbolAddress((void**)&x1,    g_x1);
    cudaGetSymbolAddress((void**)&x2,    g_x2);
    cudaGetSymbolAddress((void**)&ff,    g_ff);
    cudaGetSymbolAddress((void**)&part,  g_part);
    cudaGetSymbolAddress((void**)&stats, g_stats);
    cudaGetSymbolAddress((void**)&ah,    g_ah);
    cudaGetSymbolAddress((void**)&al,    g_al);
    cudaGetSymbolAddress((void**)&wh,    g_wh);
    cudaGetSymbolAddress((void**)&wl,    g_wl);

    cudaFuncSetAttribute(attn_mma,
                         cudaFuncAttributeMaxDynamicSharedMemorySize, AT2_SMEM);
    cudaFuncSetAttribute(gemm_mma,
                         cudaFuncAttributeMaxDynamicSharedMemorySize, GEMM_SMEM);

    const dim3 gAttn(S_ / 128, H_, B_);
    const int  gApply = (BS_ * D_ / 4) / 256;
    const int  nActD  = BS_ * D_ / 4;
    const int  nActFF = BS_ * DFF_ / 4;
    const int  nW512  = D_ * D_ / 4;
    const int  nWff   = DFF_ * D_ / 4;
    const dim3 gG512(BS_ / 128, D_ / 128);
    const dim3 gGff1(BS_ / 128, DFF_ / 128);
    const int  cvB = 256;

    #define GEMM(AH, AL, BIAS, RES, OUT, N, K, RELU, GRID) \
        gemm_mma<<<GRID, 256, GEMM_SMEM>>>(AH, AL, wh, wl, BIAS, RES, OUT, N, K, RELU)

    // ---- self-attention ----
    cvt_split<<<(nActD + cvB - 1) / cvB, cvB>>>(x, ah, al, nActD);
    cvt_head<<<(D_ * D_) / cvB, cvB>>>(m1_wq, wh, wl);
    GEMM(ah, al, m1_bq, nullptr, q, D_, D_, 0, gG512);
    cvt_head<<<(D_ * D_) / cvB, cvB>>>(m1_wk, wh, wl);
    GEMM(ah, al, m1_bk, nullptr, k, D_, D_, 0, gG512);
    cvt_head<<<(D_ * D_) / cvB, cvB>>>(m1_wv, wh, wl);
    GEMM(ah, al, m1_bv, nullptr, v, D_, D_, 0, gG512);
    attn_mma<<<gAttn, 256, AT2_SMEM>>>(q, k, v, trg_mask, ah, al);
    cvt_split<<<(nW512 + cvB - 1) / cvB, cvB>>>(m1_wo, wh, wl, nW512);
    GEMM(ah, al, m1_bo, x, res, D_, D_, 0, gG512);
    ln_partial<<<16 * B_, 256>>>(res, part);
    ln_finalize<<<1, 32>>>(part, stats);
    ln_apply<<<gApply, 256>>>(res, ln1_w, ln1_b, stats, x1);

    // ---- cross-attention ----
    cvt_split<<<(nActD + cvB - 1) / cvB, cvB>>>(x1, ah, al, nActD);
    cvt_head<<<(D_ * D_) / cvB, cvB>>>(m2_wq, wh, wl);
    GEMM(ah, al, m2_bq, nullptr, q, D_, D_, 0, gG512);
    cvt_split<<<(nActD + cvB - 1) / cvB, cvB>>>(y, ah, al, nActD);
    cvt_head<<<(D_ * D_) / cvB, cvB>>>(m2_wk, wh, wl);
    GEMM(ah, al, m2_bk, nullptr, k, D_, D_, 0, gG512);
    cvt_head<<<(D_ * D_) / cvB, cvB>>>(m2_wv, wh, wl);
    GEMM(ah, al, m2_bv, nullptr, v, D_, D_, 0, gG512);
    attn_mma<<<gAttn, 256, AT2_SMEM>>>(q, k, v, src_mask, ah, al);
    cvt_split<<<(nW512 + cvB - 1) / cvB, cvB>>>(m2_wo, wh, wl, nW512);
    GEMM(ah, al, m2_bo, x1, res, D_, D_, 0, gG512);
    ln_partial<<<16 * B_, 256>>>(res, part);
    ln_finalize<<<1, 32>>>(part, stats);
    ln_apply<<<gApply, 256>>>(res, ln2_w, ln2_b, stats, x2);

    // ---- FFN ----
    cvt_split<<<(nActD + cvB - 1) / cvB, cvB>>>(x2, ah, al, nActD);
    cvt_split<<<(nWff + cvB - 1) / cvB, cvB>>>(pw1, wh, wl, nWff);
    GEMM(ah, al, pb1, nullptr, ff, DFF_, D_, 1, gGff1);
    cvt_split<<<(nActFF + cvB - 1) / cvB, cvB>>>(ff, ah, al, nActFF);
    cvt_split<<<(nWff + cvB - 1) / cvB, cvB>>>(pw2, wh, wl, nWff);
    GEMM(ah, al, pb2, x2, res, D_, DFF_, 0, gG512);
    ln_partial<<<16 * B_, 256>>>(res, part);
    ln_finalize<<<1, 32>>>(part, stats);
    ln_apply<<<gApply, 256>>>(res, ln3_w, ln3_b, stats, out);

    #undef GEMM
}

// round 13
// speedup vs baseline: 4.2279x; 1.4981x over previous
#include <cuda_runtime.h>
#include <cuda_bf16.h>
#include <cstdint>

#define B_   8
#define S_   1024
#define D_   512
#define H_   8
#define DFF_ 2048
#define BS_  (B_ * S_)

// ---------------- scratch (no allocations allowed) ----------------
__device__ float g_res[BS_ * D_];
__device__ float g_x1[BS_ * D_];
__device__ float g_x2[BS_ * D_];
__device__ float g_part[256];
__device__ float g_stats[2 * B_];
// bf16 split operand buffers
__device__ unsigned short g_ah[BS_ * DFF_];   // staging hi (max 8192x2048)
__device__ unsigned short g_al[BS_ * DFF_];   // staging lo
__device__ unsigned short g_wh[DFF_ * D_];    // weight hi
__device__ unsigned short g_wl[DFF_ * D_];    // weight lo
__device__ unsigned short g_qh[BS_ * D_], g_ql[BS_ * D_];
__device__ unsigned short g_kh[BS_ * D_], g_kl[BS_ * D_];
__device__ unsigned short g_vh[BS_ * D_], g_vl[BS_ * D_];
__device__ unsigned short g_xsh[BS_ * D_], g_xsl[BS_ * D_];  // ln output split

// ---------------- helpers ----------------
static __device__ __forceinline__ unsigned short bfu(float x) {
    __nv_bfloat16 h = __float2bfloat16(x);
    return *reinterpret_cast<unsigned short*>(&h);
}
static __device__ __forceinline__ float ubf(unsigned short u) {
    __nv_bfloat16 h = *reinterpret_cast<__nv_bfloat16*>(&u);
    return __bfloat162float(h);
}
static __device__ __forceinline__ uint32_t smem_u32(const void* p) {
    uint32_t a;
    asm("{ .reg .u64 t; cvta.to.shared.u64 t, %1; cvt.u32.u64 %0, t; }"
        : "=r"(a) : "l"(p));
    return a;
}
static __device__ __forceinline__ void ldsm4(uint32_t* r, uint32_t addr) {
    asm volatile("ldmatrix.sync.aligned.m8n8.x4.shared.b16 {%0,%1,%2,%3}, [%4];"
        : "=r"(r[0]), "=r"(r[1]), "=r"(r[2]), "=r"(r[3]) : "r"(addr));
}
static __device__ __forceinline__ void ldsm4t(uint32_t* r, uint32_t addr) {
    asm volatile("ldmatrix.sync.aligned.m8n8.x4.trans.shared.b16 {%0,%1,%2,%3}, [%4];"
        : "=r"(r[0]), "=r"(r[1]), "=r"(r[2]), "=r"(r[3]) : "r"(addr));
}
static __device__ __forceinline__ void mma16816(
    float* c, const uint32_t* a, const uint32_t* b)
{
    asm volatile(
        "mma.sync.aligned.m16n8k16.row.col.f32.bf16.bf16.f32 "
        "{%0,%1,%2,%3}, {%4,%5,%6,%7}, {%8,%9}, {%0,%1,%2,%3};"
        : "+f"(c[0]), "+f"(c[1]), "+f"(c[2]), "+f"(c[3])
        : "r"(a[0]), "r"(a[1]), "r"(a[2]), "r"(a[3]), "r"(b[0]), "r"(b[1]));
}
static __device__ __forceinline__ void sp2(float v0, float v1,
                                           uint32_t& h2, uint32_t& l2)
{
    unsigned short h0 = bfu(v0), h1 = bfu(v1);
    unsigned short l0 = bfu(v0 - ubf(h0)), l1 = bfu(v1 - ubf(h1));
    h2 = (uint32_t)h0 | ((uint32_t)h1 << 16);
    l2 = (uint32_t)l0 | ((uint32_t)l1 << 16);
}

// =================================================================
// Operand conversion kernels
// =================================================================
__global__ __launch_bounds__(256) void cvt_split(
    const float* __restrict__ in, unsigned short* __restrict__ hi,
    unsigned short* __restrict__ lo, int n4)
{
    int i = blockIdx.x * 256 + threadIdx.x;
    if (i >= n4) return;
    float4 v = ((const float4*)in)[i];
    ushort4 H, L;
    H.x = bfu(v.x); L.x = bfu(v.x - ubf(H.x));
    H.y = bfu(v.y); L.y = bfu(v.y - ubf(H.y));
    H.z = bfu(v.z); L.z = bfu(v.z - ubf(H.z));
    H.w = bfu(v.w); L.w = bfu(v.w - ubf(H.w));
    ((ushort4*)hi)[i] = H;
    ((ushort4*)lo)[i] = L;
}

// Head weights [H, D, 64] -> trans-B layout [N=512, K=512] hi/lo
__global__ __launch_bounds__(256) void cvt_head(
    const float* __restrict__ w, unsigned short* __restrict__ hi,
    unsigned short* __restrict__ lo)
{
    int idx = blockIdx.x * 256 + threadIdx.x;
    int n = idx >> 9, k = idx & 511;
    float v = w[((size_t)(n >> 6) * 512 + k) * 64 + (n & 63)];
    unsigned short h = bfu(v);
    hi[idx] = h;
    lo[idx] = bfu(v - ubf(h));
}

// =================================================================
// bf16-split mma.sync GEMM. Output: fp32 C (opt residual) OR
// bf16 hi/lo split (Ch/Cl non-null; no residual in that mode).
// =================================================================
#define SREC 72
#define GEMM_SMEM (4 * 128 * SREC * 2)

__global__ __launch_bounds__(256) void gemm_mma(
    const unsigned short* __restrict__ Ah, const unsigned short* __restrict__ Al,
    const unsigned short* __restrict__ Bh, const unsigned short* __restrict__ Bl,
    const float* __restrict__ bias, const float* __restrict__ residual,
    float* __restrict__ C, unsigned short* __restrict__ Ch,
    unsigned short* __restrict__ Cl, int N, int K, int relu)
{
    extern __shared__ unsigned short smg[];
    unsigned short* sAh = smg;
    unsigned short* sAl = smg + 128 * SREC;
    unsigned short* sBh = smg + 2 * 128 * SREC;
    unsigned short* sBl = smg + 3 * 128 * SREC;
    const uint32_t sb = smem_u32(smg);

    const int tid = threadIdx.x;
    const int wid = tid >> 5, lane = tid & 31;
    const int m0 = blockIdx.x * 128, n0 = blockIdx.y * 128;
    const int wm = (wid & 1) * 64;
    const int wn = (wid >> 1) * 32;
    const int lr8 = lane & 7, lmt = lane >> 3;

    float acc[4][4][4] = {};

    const int lrow = tid >> 1;
    const int lq   = (tid & 1) * 4;

    for (int kc = 0; kc < K; kc += 64) {
        __syncthreads();
        #pragma unroll
        for (int i = 0; i < 4; i++) {
            int q = lq + i;
            int dst = lrow * SREC + q * 8;
            size_t gaoff = (size_t)(m0 + lrow) * K + kc + q * 8;
            size_t gboff = (size_t)(n0 + lrow) * K + kc + q * 8;
            *(uint4*)(sAh + dst) = *(const uint4*)(Ah + gaoff);
            *(uint4*)(sAl + dst) = *(const uint4*)(Al + gaoff);
            *(uint4*)(sBh + dst) = *(const uint4*)(Bh + gboff);
            *(uint4*)(sBl + dst) = *(const uint4*)(Bl + gboff);
        }
        __syncthreads();

        #pragma unroll
        for (int ks = 0; ks < 4; ks++) {
            const int k0 = ks * 16;
            uint32_t bh[4][2], bl[4][2];
            #pragma unroll
            for (int pr = 0; pr < 2; pr++) {
                uint32_t boff = (uint32_t)(wn + pr * 16 + (lmt >> 1) * 8 + lr8) * SREC
                              + k0 + (lmt & 1) * 8;
                uint32_t t[4];
                ldsm4(t, sb + 2 * (2 * 128 * SREC + boff));
                bh[pr * 2 + 0][0] = t[0]; bh[pr * 2 + 0][1] = t[1];
                bh[pr * 2 + 1][0] = t[2]; bh[pr * 2 + 1][1] = t[3];
                ldsm4(t, sb + 2 * (3 * 128 * SREC + boff));
                bl[pr * 2 + 0][0] = t[0]; bl[pr * 2 + 0][1] = t[1];
                bl[pr * 2 + 1][0] = t[2]; bl[pr * 2 + 1][1] = t[3];
            }
            #pragma unroll
            for (int mi = 0; mi < 4; mi++) {
                uint32_t aoff = (uint32_t)(wm + mi * 16 + (lmt & 1) * 8 + lr8) * SREC
                              + k0 + (lmt >> 1) * 8;
                uint32_t ah4[4], al4[4];
                ldsm4(ah4, sb + 2 * aoff);
                ldsm4(al4, sb + 2 * (128 * SREC + aoff));
                #pragma unroll
                for (int ni = 0; ni < 4; ni++) {
                    mma16816(acc[mi][ni], ah4, bh[ni]);
                    mma16816(acc[mi][ni], ah4, bl[ni]);
                    mma16816(acc[mi][ni], al4, bh[ni]);
                }
            }
        }
    }

    #pragma unroll
    for (int mi = 0; mi < 4; mi++) {
        #pragma unroll
        for (int ni = 0; ni < 4; ni++) {
            int col = n0 + wn + ni * 8 + (lane & 3) * 2;
            int r0  = m0 + wm + mi * 16 + (lane >> 2);
            float bx = bias[col], by = bias[col + 1];
            float2 v0 = { acc[mi][ni][0] + bx, acc[mi][ni][1] + by };
            float2 v1 = { acc[mi][ni][2] + bx, acc[mi][ni][3] + by };
            if (relu) {
                v0.x = fmaxf(v0.x, 0.f); v0.y = fmaxf(v0.y, 0.f);
                v1.x = fmaxf(v1.x, 0.f); v1.y = fmaxf(v1.y, 0.f);
            }
            size_t i0 = (size_t)r0 * N + col;
            size_t i1 = (size_t)(r0 + 8) * N + col;
            if (Ch) {
                uint32_t h2, l2;
                sp2(v0.x, v0.y, h2, l2);
                *(uint32_t*)(Ch + i0) = h2; *(uint32_t*)(Cl + i0) = l2;
                sp2(v1.x, v1.y, h2, l2);
                *(uint32_t*)(Ch + i1) = h2; *(uint32_t*)(Cl + i1) = l2;
            } else {
                if (residual) {
                    float2 t0 = *(const float2*)(residual + i0);
                    float2 t1 = *(const float2*)(residual + i1);
                    v0.x += t0.x; v0.y += t0.y;
                    v1.x += t1.x; v1.y += t1.y;
                }
                *(float2*)(C + i0) = v0;
                *(float2*)(C + i1) = v1;
            }
        }
    }
}

// =================================================================
// Flash attention, pure tensor-core: all operands pre-split bf16.
// Block = (128 q-rows, h, b); 8 warps x 16 rows; K/V chunks of 64.
// Scores scaled by 1/8 post-MMA (exact). Writes split output.
// smem (ushort idx): Qh 0, Ql 9216, Kh 18432, Kl 23040,
//                    Vh 27648, Vl 32256; mask fp32 @ ushort 36864.
// =================================================================
#define AT2_SMEM 77824

__global__ __launch_bounds__(256, 2) void attn_mma(
    const unsigned short* __restrict__ Qh, const unsigned short* __restrict__ Ql,
    const unsigned short* __restrict__ Kh, const unsigned short* __restrict__ Kl,
    const unsigned short* __restrict__ Vh, const unsigned short* __restrict__ Vl,
    const int* __restrict__ mask,
    unsigned short* __restrict__ Oh, unsigned short* __restrict__ Ol)
{
    const int qt = blockIdx.x, h = blockIdx.y, b = blockIdx.z;
    extern __shared__ unsigned short sma[];
    const uint32_t sb = smem_u32(sma);
    unsigned short* sQh = sma;
    unsigned short* sQl = sma + 9216;
    unsigned short* sKh = sma + 18432;
    unsigned short* sKl = sma + 23040;
    unsigned short* sVh = sma + 27648;
    unsigned short* sVl = sma + 32256;
    float* msk = (float*)(sma + 36864);

    const int tid = threadIdx.x, wid = tid >> 5, lane = tid & 31;
    const int wm = wid * 16;
    const int lr8 = lane & 7, lmt = lane >> 3;

    // ---- Q tiles (plain copies) + mask flags ----
    #pragma unroll
    for (int it = 0; it < 4; it++) {
        int t = tid + it * 256;                  // 0..1023
        int row = t >> 3, q8 = (t & 7) * 8;
        size_t g = (size_t)(b * S_ + qt * 128 + row) * D_ + h * 64 + q8;
        *(uint4*)(sQh + row * 72 + q8) = *(const uint4*)(Qh + g);
        *(uint4*)(sQl + row * 72 + q8) = *(const uint4*)(Ql + g);
        msk[t] = (mask[b * S_ + t] != 0) ? 1.0f : 0.0f;
    }

    float acc[8][4] = {};
    float m_run[2] = {-1e30f, -1e30f}, l_run[2] = {0.f, 0.f};

    for (int kc = 0; kc < 16; kc++) {
        __syncthreads();
        #pragma unroll
        for (int it = 0; it < 2; it++) {
            int t = tid + it * 256;              // 0..511
            int row = t >> 3, q8 = (t & 7) * 8;
            size_t g = (size_t)(b * S_ + kc * 64 + row) * D_ + h * 64 + q8;
            int dst = row * 72 + q8;
            *(uint4*)(sKh + dst) = *(const uint4*)(Kh + g);
            *(uint4*)(sKl + dst) = *(const uint4*)(Kl + g);
            *(uint4*)(sVh + dst) = *(const uint4*)(Vh + g);
            *(uint4*)(sVl + dst) = *(const uint4*)(Vl + g);
        }
        __syncthreads();

        // ---- scores: S = Q K^T (3 split terms) ----
        float s[8][4] = {};
        #pragma unroll
        for (int ks = 0; ks < 4; ks++) {
            uint32_t qh4[4], ql4[4];
            uint32_t aoff = (uint32_t)(wm + (lmt & 1) * 8 + lr8) * 72
                          + ks * 16 + (lmt >> 1) * 8;
            ldsm4(qh4, sb + 2 * aoff);
            ldsm4(ql4, sb + 2 * (9216 + aoff));
            #pragma unroll
            for (int pr = 0; pr < 4; pr++) {
                uint32_t boff = (uint32_t)(pr * 16 + (lmt >> 1) * 8 + lr8) * 72
                              + ks * 16 + (lmt & 1) * 8;
                uint32_t th[4], tl[4];
                ldsm4(th, sb + 2 * (18432 + boff));
                ldsm4(tl, sb + 2 * (23040 + boff));
                uint32_t bh0[2] = {th[0], th[1]}, bh1[2] = {th[2], th[3]};
                uint32_t bl0[2] = {tl[0], tl[1]}, bl1[2] = {tl[2], tl[3]};
                mma16816(s[2 * pr],     qh4, bh0);
                mma16816(s[2 * pr],     qh4, bl0);
                mma16816(s[2 * pr],     ql4, bh0);
                mma16816(s[2 * pr + 1], qh4, bh1);
                mma16816(s[2 * pr + 1], qh4, bl1);
                mma16816(s[2 * pr + 1], ql4, bh1);
            }
        }

        // ---- scale (1/sqrt(64)) + mask ----
        #pragma unroll
        for (int nt = 0; nt < 8; nt++) {
            int colb = kc * 64 + nt * 8 + 2 * (lane & 3);
            float m0 = msk[colb], m1 = msk[colb + 1];
            s[nt][0] = (m0 != 0.f) ? s[nt][0] * 0.125f : -1e10f;
            s[nt][2] = (m0 != 0.f) ? s[nt][2] * 0.125f : -1e10f;
            s[nt][1] = (m1 != 0.f) ? s[nt][1] * 0.125f : -1e10f;
            s[nt][3] = (m1 != 0.f) ? s[nt][3] * 0.125f : -1e10f;
        }

        // ---- online softmax (rows r0 = lane>>2, r1 = r0+8) ----
        float mc0 = -1e30f, mc1 = -1e30f;
        #pragma unroll
        for (int nt = 0; nt < 8; nt++) {
            mc0 = fmaxf(mc0, fmaxf(s[nt][0], s[nt][1]));
            mc1 = fmaxf(mc1, fmaxf(s[nt][2], s[nt][3]));
        }
        mc0 = fmaxf(mc0, __shfl_xor_sync(0xffffffffu, mc0, 1));
        mc0 = fmaxf(mc0, __shfl_xor_sync(0xffffffffu, mc0, 2));
        mc1 = fmaxf(mc1, __shfl_xor_sync(0xffffffffu, mc1, 1));
        mc1 = fmaxf(mc1, __shfl_xor_sync(0xffffffffu, mc1, 2));
        float mn0 = fmaxf(m_run[0], mc0), mn1 = fmaxf(m_run[1], mc1);
        float sc0 = __expf(m_run[0] - mn0), sc1 = __expf(m_run[1] - mn1);
        m_run[0] = mn0; m_run[1] = mn1;
        float ls0 = 0.f, ls1 = 0.f;
        #pragma unroll
        for (int nt = 0; nt < 8; nt++) {
            s[nt][0] = __expf(s[nt][0] - mn0); ls0 += s[nt][0];
            s[nt][1] = __expf(s[nt][1] - mn0); ls0 += s[nt][1];
            s[nt][2] = __expf(s[nt][2] - mn1); ls1 += s[nt][2];
            s[nt][3] = __expf(s[nt][3] - mn1); ls1 += s[nt][3];
        }
        ls0 += __shfl_xor_sync(0xffffffffu, ls0, 1);
        ls0 += __shfl_xor_sync(0xffffffffu, ls0, 2);
        ls1 += __shfl_xor_sync(0xffffffffu, ls1, 1);
        ls1 += __shfl_xor_sync(0xffffffffu, ls1, 2);
        l_run[0] = l_run[0] * sc0 + ls0;
        l_run[1] = l_run[1] * sc1 + ls1;
        #pragma unroll
        for (int nt = 0; nt < 8; nt++) {
            acc[nt][0] *= sc0; acc[nt][1] *= sc0;
            acc[nt][2] *= sc1; acc[nt][3] *= sc1;
        }

        // ---- O += P V (P split to bf16 hi/lo, 3 terms) ----
        #pragma unroll
        for (int ks = 0; ks < 4; ks++) {
            uint32_t aP[4], aL[4];
            sp2(s[2 * ks][0],     s[2 * ks][1],     aP[0], aL[0]);
            sp2(s[2 * ks][2],     s[2 * ks][3],     aP[1], aL[1]);
            sp2(s[2 * ks + 1][0], s[2 * ks + 1][1], aP[2], aL[2]);
            sp2(s[2 * ks + 1][2], s[2 * ks + 1][3], aP[3], aL[3]);
            #pragma unroll
            for (int pr = 0; pr < 4; pr++) {
                uint32_t boff = (uint32_t)(ks * 16 + (lmt & 1) * 8 + lr8) * 72
                              + pr * 16 + (lmt >> 1) * 8;
                uint32_t th[4], tl[4];
                ldsm4t(th, sb + 2 * (27648 + boff));
                ldsm4t(tl, sb + 2 * (32256 + boff));
                uint32_t bh0[2] = {th[0], th[1]}, bh1[2] = {th[2], th[3]};
                uint32_t bl0[2] = {tl[0], tl[1]}, bl1[2] = {tl[2], tl[3]};
                mma16816(acc[2 * pr],     aP, bh0);
                mma16816(acc[2 * pr],     aP, bl0);
                mma16816(acc[2 * pr],     aL, bh0);
                mma16816(acc[2 * pr + 1], aP, bh1);
                mma16816(acc[2 * pr + 1], aP, bl1);
                mma16816(acc[2 * pr + 1], aL, bh1);
            }
        }
    }

    // ---- output: normalize, split to bf16 hi/lo operand buffers ----
    float inv0 = 1.0f / l_run[0], inv1 = 1.0f / l_run[1];
    size_t row0 = (size_t)(b * S_ + qt * 128 + wm + (lane >> 2));
    #pragma unroll
    for (int nt = 0; nt < 8; nt++) {
        int col = h * 64 + nt * 8 + 2 * (lane & 3);
        uint32_t h2, l2;
        sp2(acc[nt][0] * inv0, acc[nt][1] * inv0, h2, l2);
        *(uint32_t*)(Oh + row0 * D_ + col) = h2;
        *(uint32_t*)(Ol + row0 * D_ + col) = l2;
        sp2(acc[nt][2] * inv1, acc[nt][3] * inv1, h2, l2);
        *(uint32_t*)(Oh + (row0 + 8) * D_ + col) = h2;
        *(uint32_t*)(Ol + (row0 + 8) * D_ + col) = l2;
    }
}

// =================================================================
// LayerNorm
// =================================================================
__global__ __launch_bounds__(256) void ln_partial(const float* __restrict__ X,
                                                  float* __restrict__ part)
{
    const int b = blockIdx.x >> 4, seg = blockIdx.x & 15;
    const float4* x = (const float4*)(X + (size_t)b * S_ * D_ + seg * 32768);
    float s = 0.f, s2 = 0.f;
    #pragma unroll 4
    for (int i = threadIdx.x; i < 8192; i += 256) {
        float4 v = x[i];
        s  += v.x + v.y + v.z + v.w;
        s2 += v.x * v.x + v.y * v.y + v.z * v.z + v.w * v.w;
    }
    #pragma unroll
    for (int o = 16; o; o >>= 1) {
        s  += __shfl_xor_sync(0xffffffffu, s, o);
        s2 += __shfl_xor_sync(0xffffffffu, s2, o);
    }
    __shared__ float ws[8], ws2[8];
    int lane = threadIdx.x & 31, wp = threadIdx.x >> 5;
    if (lane == 0) { ws[wp] = s; ws2[wp] = s2; }
    __syncthreads();
    if (threadIdx.x == 0) {
        float a = 0.f, a2 = 0.f;
        #pragma unroll
        for (int w = 0; w < 8; w++) { a += ws[w]; a2 += ws2[w]; }
        part[blockIdx.x * 2 + 0] = a;
        part[blockIdx.x * 2 + 1] = a2;
    }
}

__global__ void ln_finalize(const float* __restrict__ part, float* __restrict__ stats)
{
    int b = threadIdx.x;
    if (b < B_) {
        float s = 0.f, s2 = 0.f;
        for (int k = 0; k < 16; k++) {
            s  += part[(b * 16 + k) * 2 + 0];
            s2 += part[(b * 16 + k) * 2 + 1];
        }
        const float inv_n = 1.0f / (float)(S_ * D_);
        float mean = s * inv_n;
        float var  = s2 * inv_n - mean * mean;
        stats[b * 2 + 0] = mean;
        stats[b * 2 + 1] = rsqrtf(var + 1e-6f);
    }
}

// LN apply; optionally also emits bf16 hi/lo split of the output
__global__ __launch_bounds__(256) void ln_apply(
    const float* __restrict__ X, const float* __restrict__ w,
    const float* __restrict__ bias, const float* __restrict__ stats,
    float* __restrict__ Out, unsigned short* __restrict__ hi,
    unsigned short* __restrict__ lo)
{
    int i = blockIdx.x * 256 + threadIdx.x;
    int b  = i >> 17;
    int sd = i - (b << 17);
    float mean = stats[b * 2], rstd = stats[b * 2 + 1];
    float4 xv = ((const float4*)X)[i];
    float4 wv = ((const float4*)w)[sd];
    float4 bv = ((const float4*)bias)[sd];
    float4 o;
    o.x = (xv.x - mean) * rstd * wv.x + bv.x;
    o.y = (xv.y - mean) * rstd * wv.y + bv.y;
    o.z = (xv.z - mean) * rstd * wv.z + bv.z;
    o.w = (xv.w - mean) * rstd * wv.w + bv.w;
    ((float4*)Out)[i] = o;
    if (hi) {
        ushort4 H, L;
        H.x = bfu(o.x); L.x = bfu(o.x - ubf(H.x));
        H.y = bfu(o.y); L.y = bfu(o.y - ubf(H.y));
        H.z = bfu(o.z); L.z = bfu(o.z - ubf(H.z));
        H.w = bfu(o.w); L.w = bfu(o.w - ubf(H.w));
        ((ushort4*)hi)[i] = H;
        ((ushort4*)lo)[i] = L;
    }
}

// =================================================================
extern "C" void kernel_launch(void* const* d_in, const int* in_sizes, int n_in,
                              void* d_out, int out_size)
{
    const float* x        = (const float*)d_in[0];
    const float* y        = (const float*)d_in[1];
    const int*   src_mask = (const int*)  d_in[2];
    const int*   trg_mask = (const int*)  d_in[3];
    const float* m1_wq = (const float*)d_in[4];
    const float* m1_bq = (const float*)d_in[5];
    const float* m1_wk = (const float*)d_in[6];
    const float* m1_bk = (const float*)d_in[7];
    const float* m1_wv = (const float*)d_in[8];
    const float* m1_bv = (const float*)d_in[9];
    const float* m1_wo = (const float*)d_in[10];
    const float* m1_bo = (const float*)d_in[11];
    const float* m2_wq = (const float*)d_in[12];
    const float* m2_bq = (const float*)d_in[13];
    const float* m2_wk = (const float*)d_in[14];
    const float* m2_bk = (const float*)d_in[15];
    const float* m2_wv = (const float*)d_in[16];
    const float* m2_bv = (const float*)d_in[17];
    const float* m2_wo = (const float*)d_in[18];
    const float* m2_bo = (const float*)d_in[19];
    const float* pw1   = (const float*)d_in[20];
    const float* pb1   = (const float*)d_in[21];
    const float* pw2   = (const float*)d_in[22];
    const float* pb2   = (const float*)d_in[23];
    const float* ln1_w = (const float*)d_in[24];
    const float* ln1_b = (const float*)d_in[25];
    const float* ln2_w = (const float*)d_in[26];
    const float* ln2_b = (const float*)d_in[27];
    const float* ln3_w = (const float*)d_in[28];
    const float* ln3_b = (const float*)d_in[29];
    float* out = (float*)d_out;

    float *res, *x1, *x2, *part, *stats;
    unsigned short *ah, *al, *wh, *wl;
    unsigned short *qh, *ql, *kh, *kl, *vh, *vl, *xsh, *xsl;
    cudaGetSymbolAddress((void**)&res,   g_res);
    cudaGetSymbolAddress((void**)&x1,    g_x1);
    cudaGetSymbolAddress((void**)&x2,    g_x2);
    cudaGetSymbolAddress((void**)&part,  g_part);
    cudaGetSymbolAddress((void**)&stats, g_stats);
    cudaGetSymbolAddress((void**)&ah,    g_ah);
    cudaGetSymbolAddress((void**)&al,    g_al);
    cudaGetSymbolAddress((void**)&wh,    g_wh);
    cudaGetSymbolAddress((void**)&wl,    g_wl);
    cudaGetSymbolAddress((void**)&qh,    g_qh);
    cudaGetSymbolAddress((void**)&ql,    g_ql);
    cudaGetSymbolAddress((void**)&kh,    g_kh);
    cudaGetSymbolAddress((void**)&kl,    g_kl);
    cudaGetSymbolAddress((void**)&vh,    g_vh);
    cudaGetSymbolAddress((void**)&vl,    g_vl);
    cudaGetSymbolAddress((void**)&xsh,   g_xsh);
    cudaGetSymbolAddress((void**)&xsl,   g_xsl);

    cudaFuncSetAttribute(attn_mma,
                         cudaFuncAttributeMaxDynamicSharedMemorySize, AT2_SMEM);
    cudaFuncSetAttribute(gemm_mma,
                         cudaFuncAttributeMaxDynamicSharedMemorySize, GEMM_SMEM);

    const dim3 gAttn(S_ / 128, H_, B_);
    const int  gApply = (BS_ * D_ / 4) / 256;
    const int  nActD  = BS_ * D_ / 4;
    const int  nW512  = D_ * D_ / 4;
    const int  nWff   = DFF_ * D_ / 4;
    const dim3 gG512(BS_ / 128, D_ / 128);
    const dim3 gGff1(BS_ / 128, DFF_ / 128);
    const int  cvB = 256;

    // fp32-out GEMM (optional residual)
    #define GEMMF(AH, AL, BIAS, RES, OUT, N, K, RELU, GRID) \
        gemm_mma<<<GRID, 256, GEMM_SMEM>>>(AH, AL, wh, wl, BIAS, RES, OUT, \
                                           nullptr, nullptr, N, K, RELU)
    // split-out GEMM (no residual)
    #define GEMMS(AH, AL, BIAS, OH, OL, N, K, RELU, GRID) \
        gemm_mma<<<GRID, 256, GEMM_SMEM>>>(AH, AL, wh, wl, BIAS, nullptr, \
                                           nullptr, OH, OL, N, K, RELU)

    // ---- self-attention ----
    cvt_split<<<(nActD + cvB - 1) / cvB, cvB>>>(x, ah, al, nActD);
    cvt_head<<<(D_ * D_) / cvB, cvB>>>(m1_wq, wh, wl);
    GEMMS(ah, al, m1_bq, qh, ql, D_, D_, 0, gG512);
    cvt_head<<<(D_ * D_) / cvB, cvB>>>(m1_wk, wh, wl);
    GEMMS(ah, al, m1_bk, kh, kl, D_, D_, 0, gG512);
    cvt_head<<<(D_ * D_) / cvB, cvB>>>(m1_wv, wh, wl);
    GEMMS(ah, al, m1_bv, vh, vl, D_, D_, 0, gG512);
    attn_mma<<<gAttn, 256, AT2_SMEM>>>(qh, ql, kh, kl, vh, vl, trg_mask, ah, al);
    cvt_split<<<(nW512 + cvB - 1) / cvB, cvB>>>(m1_wo, wh, wl, nW512);
    GEMMF(ah, al, m1_bo, x, res, D_, D_, 0, gG512);
    ln_partial<<<16 * B_, 256>>>(res, part);
    ln_finalize<<<1, 32>>>(part, stats);
    ln_apply<<<gApply, 256>>>(res, ln1_w, ln1_b, stats, x1, xsh, xsl);

    // ---- cross-attention ----
    cvt_head<<<(D_ * D_) / cvB, cvB>>>(m2_wq, wh, wl);
    GEMMS(xsh, xsl, m2_bq, qh, ql, D_, D_, 0, gG512);
    cvt_split<<<(nActD + cvB - 1) / cvB, cvB>>>(y, ah, al, nActD);
    cvt_head<<<(D_ * D_) / cvB, cvB>>>(m2_wk, wh, wl);
    GEMMS(ah, al, m2_bk, kh, kl, D_, D_, 0, gG512);
    cvt_head<<<(D_ * D_) / cvB, cvB>>>(m2_wv, wh, wl);
    GEMMS(ah, al, m2_bv, vh, vl, D_, D_, 0, gG512);
    attn_mma<<<gAttn, 256, AT2_SMEM>>>(qh, ql, kh, kl, vh, vl, src_mask, ah, al);
    cvt_split<<<(nW512 + cvB - 1) / cvB, cvB>>>(m2_wo, wh, wl, nW512);
    GEMMF(ah, al, m2_bo, x1, res, D_, D_, 0, gG512);
    ln_partial<<<16 * B_, 256>>>(res, part);
    ln_finalize<<<1, 32>>>(part, stats);
    ln_apply<<<gApply, 256>>>(res, ln2_w, ln2_b, stats, x2, xsh, xsl);

    // ---- FFN ----
    cvt_split<<<(nWff + cvB - 1) / cvB, cvB>>>(pw1, wh, wl, nWff);
    GEMMS(xsh, xsl, pb1, ah, al, DFF_, D_, 1, gGff1);
    cvt_split<<<(nWff + cvB - 1) / cvB, cvB>>>(pw2, wh, wl, nWff);
    GEMMF(ah, al, pb2, x2, res, D_, DFF_, 0, gG512);
    ln_partial<<<16 * B_, 256>>>(res, part);
    ln_finalize<<<1, 32>>>(part, stats);
    ln_apply<<<gApply, 256>>>(res, ln3_w, ln3_b, stats, out, nullptr, nullptr);

    #undef GEMMF
    #undef GEMMS
}

// round 14
// speedup vs baseline: 5.1032x; 1.2070x over previous
#include <cuda_runtime.h>
#include <cuda_bf16.h>
#include <cstdint>

#define B_   8
#define S_   1024
#define D_   512
#define H_   8
#define DFF_ 2048
#define BS_  (B_ * S_)

// ---------------- scratch (no allocations allowed) ----------------
__device__ float g_res[BS_ * D_];
__device__ float g_x1[BS_ * D_];
__device__ float g_x2[BS_ * D_];
__device__ float g_part[256];
__device__ float g_stats[2 * B_];
// bf16 split operand buffers
__device__ unsigned short g_ah[BS_ * DFF_];   // staging hi (max 8192x2048)
__device__ unsigned short g_al[BS_ * DFF_];   // staging lo
__device__ unsigned short g_wh[DFF_ * D_];    // weight hi
__device__ unsigned short g_wl[DFF_ * D_];    // weight lo
__device__ unsigned short g_qh[BS_ * D_], g_ql[BS_ * D_];
__device__ unsigned short g_kh[BS_ * D_], g_kl[BS_ * D_];
__device__ unsigned short g_vh[BS_ * D_], g_vl[BS_ * D_];
__device__ unsigned short g_xsh[BS_ * D_], g_xsl[BS_ * D_];  // ln output split

// ---------------- helpers ----------------
static __device__ __forceinline__ unsigned short bfu(float x) {
    __nv_bfloat16 h = __float2bfloat16(x);
    return *reinterpret_cast<unsigned short*>(&h);
}
static __device__ __forceinline__ float ubf(unsigned short u) {
    __nv_bfloat16 h = *reinterpret_cast<__nv_bfloat16*>(&u);
    return __bfloat162float(h);
}
static __device__ __forceinline__ uint32_t smem_u32(const void* p) {
    uint32_t a;
    asm("{ .reg .u64 t; cvta.to.shared.u64 t, %1; cvt.u32.u64 %0, t; }"
        : "=r"(a) : "l"(p));
    return a;
}
static __device__ __forceinline__ void ldsm4(uint32_t* r, uint32_t addr) {
    asm volatile("ldmatrix.sync.aligned.m8n8.x4.shared.b16 {%0,%1,%2,%3}, [%4];"
        : "=r"(r[0]), "=r"(r[1]), "=r"(r[2]), "=r"(r[3]) : "r"(addr));
}
static __device__ __forceinline__ void ldsm4t(uint32_t* r, uint32_t addr) {
    asm volatile("ldmatrix.sync.aligned.m8n8.x4.trans.shared.b16 {%0,%1,%2,%3}, [%4];"
        : "=r"(r[0]), "=r"(r[1]), "=r"(r[2]), "=r"(r[3]) : "r"(addr));
}
static __device__ __forceinline__ void mma16816(
    float* c, const uint32_t* a, const uint32_t* b)
{
    asm volatile(
        "mma.sync.aligned.m16n8k16.row.col.f32.bf16.bf16.f32 "
        "{%0,%1,%2,%3}, {%4,%5,%6,%7}, {%8,%9}, {%0,%1,%2,%3};"
        : "+f"(c[0]), "+f"(c[1]), "+f"(c[2]), "+f"(c[3])
        : "r"(a[0]), "r"(a[1]), "r"(a[2]), "r"(a[3]), "r"(b[0]), "r"(b[1]));
}
static __device__ __forceinline__ void sp2(float v0, float v1,
                                           uint32_t& h2, uint32_t& l2)
{
    unsigned short h0 = bfu(v0), h1 = bfu(v1);
    unsigned short l0 = bfu(v0 - ubf(h0)), l1 = bfu(v1 - ubf(h1));
    h2 = (uint32_t)h0 | ((uint32_t)h1 << 16);
    l2 = (uint32_t)l0 | ((uint32_t)l1 << 16);
}
static __device__ __forceinline__ void cpa16(uint32_t dst, const void* src) {
    asm volatile("cp.async.cg.shared.global [%0], [%1], 16;"
                 :: "r"(dst), "l"(src));
}
static __device__ __forceinline__ void cpa_commit() {
    asm volatile("cp.async.commit_group;" ::: "memory");
}
static __device__ __forceinline__ void cpa_wait0() {
    asm volatile("cp.async.wait_group 0;" ::: "memory");
}

// =================================================================
// Operand conversion kernels
// =================================================================
__global__ __launch_bounds__(256) void cvt_split(
    const float* __restrict__ in, unsigned short* __restrict__ hi,
    unsigned short* __restrict__ lo, int n4)
{
    int i = blockIdx.x * 256 + threadIdx.x;
    if (i >= n4) return;
    float4 v = ((const float4*)in)[i];
    ushort4 H, L;
    H.x = bfu(v.x); L.x = bfu(v.x - ubf(H.x));
    H.y = bfu(v.y); L.y = bfu(v.y - ubf(H.y));
    H.z = bfu(v.z); L.z = bfu(v.z - ubf(H.z));
    H.w = bfu(v.w); L.w = bfu(v.w - ubf(H.w));
    ((ushort4*)hi)[i] = H;
    ((ushort4*)lo)[i] = L;
}

// Head weights [H, D, 64] -> trans-B layout [N=512, K=512] hi/lo
__global__ __launch_bounds__(256) void cvt_head(
    const float* __restrict__ w, unsigned short* __restrict__ hi,
    unsigned short* __restrict__ lo)
{
    int idx = blockIdx.x * 256 + threadIdx.x;
    int n = idx >> 9, k = idx & 511;
    float v = w[((size_t)(n >> 6) * 512 + k) * 64 + (n & 63)];
    unsigned short h = bfu(v);
    hi[idx] = h;
    lo[idx] = bfu(v - ubf(h));
}

// =================================================================
// bf16-split mma.sync GEMM, cp.async double-buffered (K-chunk 32).
// Output: fp32 C (opt residual) OR bf16 hi/lo split (Ch/Cl non-null).
// smem: 2 stages x 4 arrays x [128 rows x 40 ushorts] (80B rows,
// ldsm conflict-free: 16B-chunk stride 5 mod 8).
// =================================================================
#define SREC 40
#define STG  (128 * SREC)                 // ushorts per array-stage
#define GEMM_SMEM (2 * 4 * STG * 2)       // 81920 bytes

__global__ __launch_bounds__(256) void gemm_mma(
    const unsigned short* __restrict__ Ah, const unsigned short* __restrict__ Al,
    const unsigned short* __restrict__ Bh, const unsigned short* __restrict__ Bl,
    const float* __restrict__ bias, const float* __restrict__ residual,
    float* __restrict__ C, unsigned short* __restrict__ Ch,
    unsigned short* __restrict__ Cl, int N, int K, int relu)
{
    extern __shared__ unsigned short smg[];
    const uint32_t sb = smem_u32(smg);

    const int tid = threadIdx.x;
    const int wid = tid >> 5, lane = tid & 31;
    const int m0 = blockIdx.x * 128, n0 = blockIdx.y * 128;
    const int wm = (wid & 1) * 64;
    const int wn = (wid >> 1) * 32;
    const int lr8 = lane & 7, lmt = lane >> 3;

    float acc[4][4][4] = {};

    // staging: thread -> (row, quad); 2 iters cover 128 rows x 4 quads
    const int srow = tid >> 2, sq = tid & 3;

    const int nch = K >> 5;               // K / 32

    // ---- prologue: issue chunk 0 into stage 0 ----
    {
        #pragma unroll
        for (int it = 0; it < 2; it++) {
            int row = srow + it * 64;
            int dst0 = row * SREC + sq * 8;
            size_t ga = (size_t)(m0 + row) * K + sq * 8;
            size_t gb = (size_t)(n0 + row) * K + sq * 8;
            cpa16(sb + 2 * (0 * STG + dst0), Ah + ga);
            cpa16(sb + 2 * (1 * STG + dst0), Al + ga);
            cpa16(sb + 2 * (2 * STG + dst0), Bh + gb);
            cpa16(sb + 2 * (3 * STG + dst0), Bl + gb);
        }
        cpa_commit();
    }

    for (int c = 0; c < nch; c++) {
        const int cur = (c & 1) * 4 * STG;
        cpa_wait0();
        __syncthreads();
        if (c + 1 < nch) {
            const int nxt = ((c + 1) & 1) * 4 * STG;
            const int kk = (c + 1) << 5;
            #pragma unroll
            for (int it = 0; it < 2; it++) {
                int row = srow + it * 64;
                int dst0 = row * SREC + sq * 8;
                size_t ga = (size_t)(m0 + row) * K + kk + sq * 8;
                size_t gb = (size_t)(n0 + row) * K + kk + sq * 8;
                cpa16(sb + 2 * (nxt + 0 * STG + dst0), Ah + ga);
                cpa16(sb + 2 * (nxt + 1 * STG + dst0), Al + ga);
                cpa16(sb + 2 * (nxt + 2 * STG + dst0), Bh + gb);
                cpa16(sb + 2 * (nxt + 3 * STG + dst0), Bl + gb);
            }
            cpa_commit();
        }

        #pragma unroll
        for (int ks = 0; ks < 2; ks++) {
            const int k0 = ks * 16;
            uint32_t bh[4][2], bl[4][2];
            #pragma unroll
            for (int pr = 0; pr < 2; pr++) {
                uint32_t boff = (uint32_t)(wn + pr * 16 + (lmt >> 1) * 8 + lr8) * SREC
                              + k0 + (lmt & 1) * 8;
                uint32_t t[4];
                ldsm4(t, sb + 2 * (cur + 2 * STG + boff));
                bh[pr * 2 + 0][0] = t[0]; bh[pr * 2 + 0][1] = t[1];
                bh[pr * 2 + 1][0] = t[2]; bh[pr * 2 + 1][1] = t[3];
                ldsm4(t, sb + 2 * (cur + 3 * STG + boff));
                bl[pr * 2 + 0][0] = t[0]; bl[pr * 2 + 0][1] = t[1];
                bl[pr * 2 + 1][0] = t[2]; bl[pr * 2 + 1][1] = t[3];
            }
            #pragma unroll
            for (int mi = 0; mi < 4; mi++) {
                uint32_t aoff = (uint32_t)(wm + mi * 16 + (lmt & 1) * 8 + lr8) * SREC
                              + k0 + (lmt >> 1) * 8;
                uint32_t ah4[4], al4[4];
                ldsm4(ah4, sb + 2 * (cur + aoff));
                ldsm4(al4, sb + 2 * (cur + 1 * STG + aoff));
                #pragma unroll
                for (int ni = 0; ni < 4; ni++) {
                    mma16816(acc[mi][ni], ah4, bh[ni]);
                    mma16816(acc[mi][ni], ah4, bl[ni]);
                    mma16816(acc[mi][ni], al4, bh[ni]);
                }
            }
        }
        __syncthreads();
    }

    #pragma unroll
    for (int mi = 0; mi < 4; mi++) {
        #pragma unroll
        for (int ni = 0; ni < 4; ni++) {
            int col = n0 + wn + ni * 8 + (lane & 3) * 2;
            int r0  = m0 + wm + mi * 16 + (lane >> 2);
            float bx = bias[col], by = bias[col + 1];
            float2 v0 = { acc[mi][ni][0] + bx, acc[mi][ni][1] + by };
            float2 v1 = { acc[mi][ni][2] + bx, acc[mi][ni][3] + by };
            if (relu) {
                v0.x = fmaxf(v0.x, 0.f); v0.y = fmaxf(v0.y, 0.f);
                v1.x = fmaxf(v1.x, 0.f); v1.y = fmaxf(v1.y, 0.f);
            }
            size_t i0 = (size_t)r0 * N + col;
            size_t i1 = (size_t)(r0 + 8) * N + col;
            if (Ch) {
                uint32_t h2, l2;
                sp2(v0.x, v0.y, h2, l2);
                *(uint32_t*)(Ch + i0) = h2; *(uint32_t*)(Cl + i0) = l2;
                sp2(v1.x, v1.y, h2, l2);
                *(uint32_t*)(Ch + i1) = h2; *(uint32_t*)(Cl + i1) = l2;
            } else {
                if (residual) {
                    float2 t0 = *(const float2*)(residual + i0);
                    float2 t1 = *(const float2*)(residual + i1);
                    v0.x += t0.x; v0.y += t0.y;
                    v1.x += t1.x; v1.y += t1.y;
                }
                *(float2*)(C + i0) = v0;
                *(float2*)(C + i1) = v1;
            }
        }
    }
}

// =================================================================
// Flash attention, pure tensor-core (unchanged from round 12).
// =================================================================
#define AT2_SMEM 77824

__global__ __launch_bounds__(256, 2) void attn_mma(
    const unsigned short* __restrict__ Qh, const unsigned short* __restrict__ Ql,
    const unsigned short* __restrict__ Kh, const unsigned short* __restrict__ Kl,
    const unsigned short* __restrict__ Vh, const unsigned short* __restrict__ Vl,
    const int* __restrict__ mask,
    unsigned short* __restrict__ Oh, unsigned short* __restrict__ Ol)
{
    const int qt = blockIdx.x, h = blockIdx.y, b = blockIdx.z;
    extern __shared__ unsigned short sma[];
    const uint32_t sb = smem_u32(sma);
    unsigned short* sQh = sma;
    unsigned short* sQl = sma + 9216;
    unsigned short* sKh = sma + 18432;
    unsigned short* sKl = sma + 23040;
    unsigned short* sVh = sma + 27648;
    unsigned short* sVl = sma + 32256;
    float* msk = (float*)(sma + 36864);

    const int tid = threadIdx.x, wid = tid >> 5, lane = tid & 31;
    const int wm = wid * 16;
    const int lr8 = lane & 7, lmt = lane >> 3;

    #pragma unroll
    for (int it = 0; it < 4; it++) {
        int t = tid + it * 256;
        int row = t >> 3, q8 = (t & 7) * 8;
        size_t g = (size_t)(b * S_ + qt * 128 + row) * D_ + h * 64 + q8;
        *(uint4*)(sQh + row * 72 + q8) = *(const uint4*)(Qh + g);
        *(uint4*)(sQl + row * 72 + q8) = *(const uint4*)(Ql + g);
        msk[t] = (mask[b * S_ + t] != 0) ? 1.0f : 0.0f;
    }

    float acc[8][4] = {};
    float m_run[2] = {-1e30f, -1e30f}, l_run[2] = {0.f, 0.f};

    for (int kc = 0; kc < 16; kc++) {
        __syncthreads();
        #pragma unroll
        for (int it = 0; it < 2; it++) {
            int t = tid + it * 256;
            int row = t >> 3, q8 = (t & 7) * 8;
            size_t g = (size_t)(b * S_ + kc * 64 + row) * D_ + h * 64 + q8;
            int dst = row * 72 + q8;
            *(uint4*)(sKh + dst) = *(const uint4*)(Kh + g);
            *(uint4*)(sKl + dst) = *(const uint4*)(Kl + g);
            *(uint4*)(sVh + dst) = *(const uint4*)(Vh + g);
            *(uint4*)(sVl + dst) = *(const uint4*)(Vl + g);
        }
        __syncthreads();

        float s[8][4] = {};
        #pragma unroll
        for (int ks = 0; ks < 4; ks++) {
            uint32_t qh4[4], ql4[4];
            uint32_t aoff = (uint32_t)(wm + (lmt & 1) * 8 + lr8) * 72
                          + ks * 16 + (lmt >> 1) * 8;
            ldsm4(qh4, sb + 2 * aoff);
            ldsm4(ql4, sb + 2 * (9216 + aoff));
            #pragma unroll
            for (int pr = 0; pr < 4; pr++) {
                uint32_t boff = (uint32_t)(pr * 16 + (lmt >> 1) * 8 + lr8) * 72
                              + ks * 16 + (lmt & 1) * 8;
                uint32_t th[4], tl[4];
                ldsm4(th, sb + 2 * (18432 + boff));
                ldsm4(tl, sb + 2 * (23040 + boff));
                uint32_t bh0[2] = {th[0], th[1]}, bh1[2] = {th[2], th[3]};
                uint32_t bl0[2] = {tl[0], tl[1]}, bl1[2] = {tl[2], tl[3]};
                mma16816(s[2 * pr],     qh4, bh0);
                mma16816(s[2 * pr],     qh4, bl0);
                mma16816(s[2 * pr],     ql4, bh0);
                mma16816(s[2 * pr + 1], qh4, bh1);
                mma16816(s[2 * pr + 1], qh4, bl1);
                mma16816(s[2 * pr + 1], ql4, bh1);
            }
        }

        #pragma unroll
        for (int nt = 0; nt < 8; nt++) {
            int colb = kc * 64 + nt * 8 + 2 * (lane & 3);
            float m0 = msk[colb], m1 = msk[colb + 1];
            s[nt][0] = (m0 != 0.f) ? s[nt][0] * 0.125f : -1e10f;
            s[nt][2] = (m0 != 0.f) ? s[nt][2] * 0.125f : -1e10f;
            s[nt][1] = (m1 != 0.f) ? s[nt][1] * 0.125f : -1e10f;
            s[nt][3] = (m1 != 0.f) ? s[nt][3] * 0.125f : -1e10f;
        }

        float mc0 = -1e30f, mc1 = -1e30f;
        #pragma unroll
        for (int nt = 0; nt < 8; nt++) {
            mc0 = fmaxf(mc0, fmaxf(s[nt][0], s[nt][1]));
            mc1 = fmaxf(mc1, fmaxf(s[nt][2], s[nt][3]));
        }
        mc0 = fmaxf(mc0, __shfl_xor_sync(0xffffffffu, mc0, 1));
        mc0 = fmaxf(mc0, __shfl_xor_sync(0xffffffffu, mc0, 2));
        mc1 = fmaxf(mc1, __shfl_xor_sync(0xffffffffu, mc1, 1));
        mc1 = fmaxf(mc1, __shfl_xor_sync(0xffffffffu, mc1, 2));
        float mn0 = fmaxf(m_run[0], mc0), mn1 = fmaxf(m_run[1], mc1);
        float sc0 = __expf(m_run[0] - mn0), sc1 = __expf(m_run[1] - mn1);
        m_run[0] = mn0; m_run[1] = mn1;
        float ls0 = 0.f, ls1 = 0.f;
        #pragma unroll
        for (int nt = 0; nt < 8; nt++) {
            s[nt][0] = __expf(s[nt][0] - mn0); ls0 += s[nt][0];
            s[nt][1] = __expf(s[nt][1] - mn0); ls0 += s[nt][1];
            s[nt][2] = __expf(s[nt][2] - mn1); ls1 += s[nt][2];
            s[nt][3] = __expf(s[nt][3] - mn1); ls1 += s[nt][3];
        }
        ls0 += __shfl_xor_sync(0xffffffffu, ls0, 1);
        ls0 += __shfl_xor_sync(0xffffffffu, ls0, 2);
        ls1 += __shfl_xor_sync(0xffffffffu, ls1, 1);
        ls1 += __shfl_xor_sync(0xffffffffu, ls1, 2);
        l_run[0] = l_run[0] * sc0 + ls0;
        l_run[1] = l_run[1] * sc1 + ls1;
        #pragma unroll
        for (int nt = 0; nt < 8; nt++) {
            acc[nt][0] *= sc0; acc[nt][1] *= sc0;
            acc[nt][2] *= sc1; acc[nt][3] *= sc1;
        }

        #pragma unroll
        for (int ks = 0; ks < 4; ks++) {
            uint32_t aP[4], aL[4];
            sp2(s[2 * ks][0],     s[2 * ks][1],     aP[0], aL[0]);
            sp2(s[2 * ks][2],     s[2 * ks][3],     aP[1], aL[1]);
            sp2(s[2 * ks + 1][0], s[2 * ks + 1][1], aP[2], aL[2]);
            sp2(s[2 * ks + 1][2], s[2 * ks + 1][3], aP[3], aL[3]);
            #pragma unroll
            for (int pr = 0; pr < 4; pr++) {
                uint32_t boff = (uint32_t)(ks * 16 + (lmt & 1) * 8 + lr8) * 72
                              + pr * 16 + (lmt >> 1) * 8;
                uint32_t th[4], tl[4];
                ldsm4t(th, sb + 2 * (27648 + boff));
                ldsm4t(tl, sb + 2 * (32256 + boff));
                uint32_t bh0[2] = {th[0], th[1]}, bh1[2] = {th[2], th[3]};
                uint32_t bl0[2] = {tl[0], tl[1]}, bl1[2] = {tl[2], tl[3]};
                mma16816(acc[2 * pr],     aP, bh0);
                mma16816(acc[2 * pr],     aP, bl0);
                mma16816(acc[2 * pr],     aL, bh0);
                mma16816(acc[2 * pr + 1], aP, bh1);
                mma16816(acc[2 * pr + 1], aP, bl1);
                mma16816(acc[2 * pr + 1], aL, bh1);
            }
        }
    }

    float inv0 = 1.0f / l_run[0], inv1 = 1.0f / l_run[1];
    size_t row0 = (size_t)(b * S_ + qt * 128 + wm + (lane >> 2));
    #pragma unroll
    for (int nt = 0; nt < 8; nt++) {
        int col = h * 64 + nt * 8 + 2 * (lane & 3);
        uint32_t h2, l2;
        sp2(acc[nt][0] * inv0, acc[nt][1] * inv0, h2, l2);
        *(uint32_t*)(Oh + row0 * D_ + col) = h2;
        *(uint32_t*)(Ol + row0 * D_ + col) = l2;
        sp2(acc[nt][2] * inv1, acc[nt][3] * inv1, h2, l2);
        *(uint32_t*)(Oh + (row0 + 8) * D_ + col) = h2;
        *(uint32_t*)(Ol + (row0 + 8) * D_ + col) = l2;
    }
}

// =================================================================
// LayerNorm
// =================================================================
__global__ __launch_bounds__(256) void ln_partial(const float* __restrict__ X,
                                                  float* __restrict__ part)
{
    const int b = blockIdx.x >> 4, seg = blockIdx.x & 15;
    const float4* x = (const float4*)(X + (size_t)b * S_ * D_ + seg * 32768);
    float s = 0.f, s2 = 0.f;
    #pragma unroll 4
    for (int i = threadIdx.x; i < 8192; i += 256) {
        float4 v = x[i];
        s  += v.x + v.y + v.z + v.w;
        s2 += v.x * v.x + v.y * v.y + v.z * v.z + v.w * v.w;
    }
    #pragma unroll
    for (int o = 16; o; o >>= 1) {
        s  += __shfl_xor_sync(0xffffffffu, s, o);
        s2 += __shfl_xor_sync(0xffffffffu, s2, o);
    }
    __shared__ float ws[8], ws2[8];
    int lane = threadIdx.x & 31, wp = threadIdx.x >> 5;
    if (lane == 0) { ws[wp] = s; ws2[wp] = s2; }
    __syncthreads();
    if (threadIdx.x == 0) {
        float a = 0.f, a2 = 0.f;
        #pragma unroll
        for (int w = 0; w < 8; w++) { a += ws[w]; a2 += ws2[w]; }
        part[blockIdx.x * 2 + 0] = a;
        part[blockIdx.x * 2 + 1] = a2;
    }
}

__global__ void ln_finalize(const float* __restrict__ part, float* __restrict__ stats)
{
    int b = threadIdx.x;
    if (b < B_) {
        float s = 0.f, s2 = 0.f;
        for (int k = 0; k < 16; k++) {
            s  += part[(b * 16 + k) * 2 + 0];
            s2 += part[(b * 16 + k) * 2 + 1];
        }
        const float inv_n = 1.0f / (float)(S_ * D_);
        float mean = s * inv_n;
        float var  = s2 * inv_n - mean * mean;
        stats[b * 2 + 0] = mean;
        stats[b * 2 + 1] = rsqrtf(var + 1e-6f);
    }
}

__global__ __launch_bounds__(256) void ln_apply(
    const float* __restrict__ X, const float* __restrict__ w,
    const float* __restrict__ bias, const float* __restrict__ stats,
    float* __restrict__ Out, unsigned short* __restrict__ hi,
    unsigned short* __restrict__ lo)
{
    int i = blockIdx.x * 256 + threadIdx.x;
    int b  = i >> 17;
    int sd = i - (b << 17);
    float mean = stats[b * 2], rstd = stats[b * 2 + 1];
    float4 xv = ((const float4*)X)[i];
    float4 wv = ((const float4*)w)[sd];
    float4 bv = ((const float4*)bias)[sd];
    float4 o;
    o.x = (xv.x - mean) * rstd * wv.x + bv.x;
    o.y = (xv.y - mean) * rstd * wv.y + bv.y;
    o.z = (xv.z - mean) * rstd * wv.z + bv.z;
    o.w = (xv.w - mean) * rstd * wv.w + bv.w;
    ((float4*)Out)[i] = o;
    if (hi) {
        ushort4 H, L;
        H.x = bfu(o.x); L.x = bfu(o.x - ubf(H.x));
        H.y = bfu(o.y); L.y = bfu(o.y - ubf(H.y));
        H.z = bfu(o.z); L.z = bfu(o.z - ubf(H.z));
        H.w = bfu(o.w); L.w = bfu(o.w - ubf(H.w));
        ((ushort4*)hi)[i] = H;
        ((ushort4*)lo)[i] = L;
    }
}

// =================================================================
extern "C" void kernel_launch(void* const* d_in, const int* in_sizes, int n_in,
                              void* d_out, int out_size)
{
    const float* x        = (const float*)d_in[0];
    const float* y        = (const float*)d_in[1];
    const int*   src_mask = (const int*)  d_in[2];
    const int*   trg_mask = (const int*)  d_in[3];
    const float* m1_wq = (const float*)d_in[4];
    const float* m1_bq = (const float*)d_in[5];
    const float* m1_wk = (const float*)d_in[6];
    const float* m1_bk = (const float*)d_in[7];
    const float* m1_wv = (const float*)d_in[8];
    const float* m1_bv = (const float*)d_in[9];
    const float* m1_wo = (const float*)d_in[10];
    const float* m1_bo = (const float*)d_in[11];
    const float* m2_wq = (const float*)d_in[12];
    const float* m2_bq = (const float*)d_in[13];
    const float* m2_wk = (const float*)d_in[14];
    const float* m2_bk = (const float*)d_in[15];
    const float* m2_wv = (const float*)d_in[16];
    const float* m2_bv = (const float*)d_in[17];
    const float* m2_wo = (const float*)d_in[18];
    const float* m2_bo = (const float*)d_in[19];
    const float* pw1   = (const float*)d_in[20];
    const float* pb1   = (const float*)d_in[21];
    const float* pw2   = (const float*)d_in[22];
    const float* pb2   = (const float*)d_in[23];
    const float* ln1_w = (const float*)d_in[24];
    const float* ln1_b = (const float*)d_in[25];
    const float* ln2_w = (const float*)d_in[26];
    const float* ln2_b = (const float*)d_in[27];
    const float* ln3_w = (const float*)d_in[28];
    const float* ln3_b = (const float*)d_in[29];
    float* out = (float*)d_out;

    float *res, *x1, *x2, *part, *stats;
    unsigned short *ah, *al, *wh, *wl;
    unsigned short *qh, *ql, *kh, *kl, *vh, *vl, *xsh, *xsl;
    cudaGetSymbolAddress((void**)&res,   g_res);
    cudaGetSymbolAddress((void**)&x1,    g_x1);
    cudaGetSymbolAddress((void**)&x2,    g_x2);
    cudaGetSymbolAddress((void**)&part,  g_part);
    cudaGetSymbolAddress((void**)&stats, g_stats);
    cudaGetSymbolAddress((void**)&ah,    g_ah);
    cudaGetSymbolAddress((void**)&al,    g_al);
    cudaGetSymbolAddress((void**)&wh,    g_wh);
    cudaGetSymbolAddress((void**)&wl,    g_wl);
    cudaGetSymbolAddress((void**)&qh,    g_qh);
    cudaGetSymbolAddress((void**)&ql,    g_ql);
    cudaGetSymbolAddress((void**)&kh,    g_kh);
    cudaGetSymbolAddress((void**)&kl,    g_kl);
    cudaGetSymbolAddress((void**)&vh,    g_vh);
    cudaGetSymbolAddress((void**)&vl,    g_vl);
    cudaGetSymbolAddress((void**)&xsh,   g_xsh);
    cudaGetSymbolAddress((void**)&xsl,   g_xsl);

    cudaFuncSetAttribute(attn_mma,
                         cudaFuncAttributeMaxDynamicSharedMemorySize, AT2_SMEM);
    cudaFuncSetAttribute(gemm_mma,
                         cudaFuncAttributeMaxDynamicSharedMemorySize, GEMM_SMEM);

    const dim3 gAttn(S_ / 128, H_, B_);
    const int  gApply = (BS_ * D_ / 4) / 256;
    const int  nActD  = BS_ * D_ / 4;
    const int  nW512  = D_ * D_ / 4;
    const int  nWff   = DFF_ * D_ / 4;
    const dim3 gG512(BS_ / 128, D_ / 128);
    const dim3 gGff1(BS_ / 128, DFF_ / 128);
    const int  cvB = 256;

    #define GEMMF(AH, AL, BIAS, RES, OUT, N, K, RELU, GRID) \
        gemm_mma<<<GRID, 256, GEMM_SMEM>>>(AH, AL, wh, wl, BIAS, RES, OUT, \
                                           nullptr, nullptr, N, K, RELU)
    #define GEMMS(AH, AL, BIAS, OH, OL, N, K, RELU, GRID) \
        gemm_mma<<<GRID, 256, GEMM_SMEM>>>(AH, AL, wh, wl, BIAS, nullptr, \
                                           nullptr, OH, OL, N, K, RELU)

    // ---- self-attention ----
    cvt_split<<<(nActD + cvB - 1) / cvB, cvB>>>(x, ah, al, nActD);
    cvt_head<<<(D_ * D_) / cvB, cvB>>>(m1_wq, wh, wl);
    GEMMS(ah, al, m1_bq, qh, ql, D_, D_, 0, gG512);
    cvt_head<<<(D_ * D_) / cvB, cvB>>>(m1_wk, wh, wl);
    GEMMS(ah, al, m1_bk, kh, kl, D_, D_, 0, gG512);
    cvt_head<<<(D_ * D_) / cvB, cvB>>>(m1_wv, wh, wl);
    GEMMS(ah, al, m1_bv, vh, vl, D_, D_, 0, gG512);
    attn_mma<<<gAttn, 256, AT2_SMEM>>>(qh, ql, kh, kl, vh, vl, trg_mask, ah, al);
    cvt_split<<<(nW512 + cvB - 1) / cvB, cvB>>>(m1_wo, wh, wl, nW512);
    GEMMF(ah, al, m1_bo, x, res, D_, D_, 0, gG512);
    ln_partial<<<16 * B_, 256>>>(res, part);
    ln_finalize<<<1, 32>>>(part, stats);
    ln_apply<<<gApply, 256>>>(res, ln1_w, ln1_b, stats, x1, xsh, xsl);

    // ---- cross-attention ----
    cvt_head<<<(D_ * D_) / cvB, cvB>>>(m2_wq, wh, wl);
    GEMMS(xsh, xsl, m2_bq, qh, ql, D_, D_, 0, gG512);
    cvt_split<<<(nActD + cvB - 1) / cvB, cvB>>>(y, ah, al, nActD);
    cvt_head<<<(D_ * D_) / cvB, cvB>>>(m2_wk, wh, wl);
    GEMMS(ah, al, m2_bk, kh, kl, D_, D_, 0, gG512);
    cvt_head<<<(D_ * D_) / cvB, cvB>>>(m2_wv, wh, wl);
    GEMMS(ah, al, m2_bv, vh, vl, D_, D_, 0, gG512);
    attn_mma<<<gAttn, 256, AT2_SMEM>>>(qh, ql, kh, kl, vh, vl, src_mask, ah, al);
    cvt_split<<<(nW512 + cvB - 1) / cvB, cvB>>>(m2_wo, wh, wl, nW512);
    GEMMF(ah, al, m2_bo, x1, res, D_, D_, 0, gG512);
    ln_partial<<<16 * B_, 256>>>(res, part);
    ln_finalize<<<1, 32>>>(part, stats);
    ln_apply<<<gApply, 256>>>(res, ln2_w, ln2_b, stats, x2, xsh, xsl);

    // ---- FFN ----
    cvt_split<<<(nWff + cvB - 1) / cvB, cvB>>>(pw1, wh, wl, nWff);
    GEMMS(xsh, xsl, pb1, ah, al, DFF_, D_, 1, gGff1);
    cvt_split<<<(nWff + cvB - 1) / cvB, cvB>>>(pw2, wh, wl, nWff);
    GEMMF(ah, al, pb2, x2, res, D_, DFF_, 0, gG512);
    ln_partial<<<16 * B_, 256>>>(res, part);
    ln_finalize<<<1, 32>>>(part, stats);
    ln_apply<<<gApply, 256>>>(res, ln3_w, ln3_b, stats, out, nullptr, nullptr);

    #undef GEMMF
    #undef GEMMS
}

// round 15
// speedup vs baseline: 5.2349x; 1.0258x over previous
#include <cuda_runtime.h>
#include <cuda_bf16.h>
#include <cstdint>

#define B_   8
#define S_   1024
#define D_   512
#define H_   8
#define DFF_ 2048
#define BS_  (B_ * S_)

// ---------------- scratch (no allocations allowed) ----------------
__device__ float g_res[BS_ * D_];
__device__ float g_x1[BS_ * D_];
__device__ float g_x2[BS_ * D_];
__device__ float g_part[512];            // 256 CTA slots x {sum, sumsq}
__device__ float g_stats[2 * B_];
// bf16 split operand buffers
__device__ unsigned short g_ah[BS_ * DFF_];
__device__ unsigned short g_al[BS_ * DFF_];
__device__ unsigned short g_wh[DFF_ * D_];
__device__ unsigned short g_wl[DFF_ * D_];
__device__ unsigned short g_qh[BS_ * D_], g_ql[BS_ * D_];
__device__ unsigned short g_kh[BS_ * D_], g_kl[BS_ * D_];
__device__ unsigned short g_vh[BS_ * D_], g_vl[BS_ * D_];
__device__ unsigned short g_xsh[BS_ * D_], g_xsl[BS_ * D_];

// ---------------- helpers ----------------
static __device__ __forceinline__ unsigned short bfu(float x) {
    __nv_bfloat16 h = __float2bfloat16(x);
    return *reinterpret_cast<unsigned short*>(&h);
}
static __device__ __forceinline__ float ubf(unsigned short u) {
    __nv_bfloat16 h = *reinterpret_cast<__nv_bfloat16*>(&u);
    return __bfloat162float(h);
}
static __device__ __forceinline__ uint32_t smem_u32(const void* p) {
    uint32_t a;
    asm("{ .reg .u64 t; cvta.to.shared.u64 t, %1; cvt.u32.u64 %0, t; }"
        : "=r"(a) : "l"(p));
    return a;
}
static __device__ __forceinline__ void ldsm4(uint32_t* r, uint32_t addr) {
    asm volatile("ldmatrix.sync.aligned.m8n8.x4.shared.b16 {%0,%1,%2,%3}, [%4];"
        : "=r"(r[0]), "=r"(r[1]), "=r"(r[2]), "=r"(r[3]) : "r"(addr));
}
static __device__ __forceinline__ void ldsm4t(uint32_t* r, uint32_t addr) {
    asm volatile("ldmatrix.sync.aligned.m8n8.x4.trans.shared.b16 {%0,%1,%2,%3}, [%4];"
        : "=r"(r[0]), "=r"(r[1]), "=r"(r[2]), "=r"(r[3]) : "r"(addr));
}
static __device__ __forceinline__ void mma16816(
    float* c, const uint32_t* a, const uint32_t* b)
{
    asm volatile(
        "mma.sync.aligned.m16n8k16.row.col.f32.bf16.bf16.f32 "
        "{%0,%1,%2,%3}, {%4,%5,%6,%7}, {%8,%9}, {%0,%1,%2,%3};"
        : "+f"(c[0]), "+f"(c[1]), "+f"(c[2]), "+f"(c[3])
        : "r"(a[0]), "r"(a[1]), "r"(a[2]), "r"(a[3]), "r"(b[0]), "r"(b[1]));
}
static __device__ __forceinline__ void sp2(float v0, float v1,
                                           uint32_t& h2, uint32_t& l2)
{
    unsigned short h0 = bfu(v0), h1 = bfu(v1);
    unsigned short l0 = bfu(v0 - ubf(h0)), l1 = bfu(v1 - ubf(h1));
    h2 = (uint32_t)h0 | ((uint32_t)h1 << 16);
    l2 = (uint32_t)l0 | ((uint32_t)l1 << 16);
}
static __device__ __forceinline__ void cpa16(uint32_t dst, const void* src) {
    asm volatile("cp.async.cg.shared.global [%0], [%1], 16;"
                 :: "r"(dst), "l"(src));
}
static __device__ __forceinline__ void cpa_commit() {
    asm volatile("cp.async.commit_group;" ::: "memory");
}
static __device__ __forceinline__ void cpa_wait0() {
    asm volatile("cp.async.wait_group 0;" ::: "memory");
}

// =================================================================
// Operand conversion kernels
// =================================================================
__global__ __launch_bounds__(256) void cvt_split(
    const float* __restrict__ in, unsigned short* __restrict__ hi,
    unsigned short* __restrict__ lo, int n4)
{
    int i = blockIdx.x * 256 + threadIdx.x;
    if (i >= n4) return;
    float4 v = ((const float4*)in)[i];
    ushort4 H, L;
    H.x = bfu(v.x); L.x = bfu(v.x - ubf(H.x));
    H.y = bfu(v.y); L.y = bfu(v.y - ubf(H.y));
    H.z = bfu(v.z); L.z = bfu(v.z - ubf(H.z));
    H.w = bfu(v.w); L.w = bfu(v.w - ubf(H.w));
    ((ushort4*)hi)[i] = H;
    ((ushort4*)lo)[i] = L;
}

// Head weights [H, D, 64] -> trans-B layout [N=512, K=512] hi/lo
__global__ __launch_bounds__(256) void cvt_head(
    const float* __restrict__ w, unsigned short* __restrict__ hi,
    unsigned short* __restrict__ lo)
{
    int idx = blockIdx.x * 256 + threadIdx.x;
    int n = idx >> 9, k = idx & 511;
    float v = w[((size_t)(n >> 6) * 512 + k) * 64 + (n & 63)];
    unsigned short h = bfu(v);
    hi[idx] = h;
    lo[idx] = bfu(v - ubf(h));
}

// =================================================================
// bf16-split mma.sync GEMM, cp.async double-buffered (K-chunk 32).
// Output: fp32 C (opt residual, opt per-CTA LN partial sums) OR
// bf16 hi/lo split (Ch/Cl non-null).
// =================================================================
#define SREC 40
#define STG  (128 * SREC)
#define GEMM_SMEM (2 * 4 * STG * 2)       // 81920 bytes

__global__ __launch_bounds__(256) void gemm_mma(
    const unsigned short* __restrict__ Ah, const unsigned short* __restrict__ Al,
    const unsigned short* __restrict__ Bh, const unsigned short* __restrict__ Bl,
    const float* __restrict__ bias, const float* __restrict__ residual,
    float* __restrict__ C, unsigned short* __restrict__ Ch,
    unsigned short* __restrict__ Cl, float* __restrict__ part,
    int N, int K, int relu)
{
    extern __shared__ unsigned short smg[];
    const uint32_t sb = smem_u32(smg);

    const int tid = threadIdx.x;
    const int wid = tid >> 5, lane = tid & 31;
    const int m0 = blockIdx.x * 128, n0 = blockIdx.y * 128;
    const int wm = (wid & 1) * 64;
    const int wn = (wid >> 1) * 32;
    const int lr8 = lane & 7, lmt = lane >> 3;

    float acc[4][4][4] = {};

    const int srow = tid >> 2, sq = tid & 3;
    const int nch = K >> 5;

    {
        #pragma unroll
        for (int it = 0; it < 2; it++) {
            int row = srow + it * 64;
            int dst0 = row * SREC + sq * 8;
            size_t ga = (size_t)(m0 + row) * K + sq * 8;
            size_t gb = (size_t)(n0 + row) * K + sq * 8;
            cpa16(sb + 2 * (0 * STG + dst0), Ah + ga);
            cpa16(sb + 2 * (1 * STG + dst0), Al + ga);
            cpa16(sb + 2 * (2 * STG + dst0), Bh + gb);
            cpa16(sb + 2 * (3 * STG + dst0), Bl + gb);
        }
        cpa_commit();
    }

    for (int c = 0; c < nch; c++) {
        const int cur = (c & 1) * 4 * STG;
        cpa_wait0();
        __syncthreads();
        if (c + 1 < nch) {
            const int nxt = ((c + 1) & 1) * 4 * STG;
            const int kk = (c + 1) << 5;
            #pragma unroll
            for (int it = 0; it < 2; it++) {
                int row = srow + it * 64;
                int dst0 = row * SREC + sq * 8;
                size_t ga = (size_t)(m0 + row) * K + kk + sq * 8;
                size_t gb = (size_t)(n0 + row) * K + kk + sq * 8;
                cpa16(sb + 2 * (nxt + 0 * STG + dst0), Ah + ga);
                cpa16(sb + 2 * (nxt + 1 * STG + dst0), Al + ga);
                cpa16(sb + 2 * (nxt + 2 * STG + dst0), Bh + gb);
                cpa16(sb + 2 * (nxt + 3 * STG + dst0), Bl + gb);
            }
            cpa_commit();
        }

        #pragma unroll
        for (int ks = 0; ks < 2; ks++) {
            const int k0 = ks * 16;
            uint32_t bh[4][2], bl[4][2];
            #pragma unroll
            for (int pr = 0; pr < 2; pr++) {
                uint32_t boff = (uint32_t)(wn + pr * 16 + (lmt >> 1) * 8 + lr8) * SREC
                              + k0 + (lmt & 1) * 8;
                uint32_t t[4];
                ldsm4(t, sb + 2 * (cur + 2 * STG + boff));
                bh[pr * 2 + 0][0] = t[0]; bh[pr * 2 + 0][1] = t[1];
                bh[pr * 2 + 1][0] = t[2]; bh[pr * 2 + 1][1] = t[3];
                ldsm4(t, sb + 2 * (cur + 3 * STG + boff));
                bl[pr * 2 + 0][0] = t[0]; bl[pr * 2 + 0][1] = t[1];
                bl[pr * 2 + 1][0] = t[2]; bl[pr * 2 + 1][1] = t[3];
            }
            #pragma unroll
            for (int mi = 0; mi < 4; mi++) {
                uint32_t aoff = (uint32_t)(wm + mi * 16 + (lmt & 1) * 8 + lr8) * SREC
                              + k0 + (lmt >> 1) * 8;
                uint32_t ah4[4], al4[4];
                ldsm4(ah4, sb + 2 * (cur + aoff));
                ldsm4(al4, sb + 2 * (cur + 1 * STG + aoff));
                #pragma unroll
                for (int ni = 0; ni < 4; ni++) {
                    mma16816(acc[mi][ni], ah4, bh[ni]);
                    mma16816(acc[mi][ni], ah4, bl[ni]);
                    mma16816(acc[mi][ni], al4, bh[ni]);
                }
            }
        }
        __syncthreads();
    }

    float ssum = 0.f, ssq = 0.f;
    #pragma unroll
    for (int mi = 0; mi < 4; mi++) {
        #pragma unroll
        for (int ni = 0; ni < 4; ni++) {
            int col = n0 + wn + ni * 8 + (lane & 3) * 2;
            int r0  = m0 + wm + mi * 16 + (lane >> 2);
            float bx = bias[col], by = bias[col + 1];
            float2 v0 = { acc[mi][ni][0] + bx, acc[mi][ni][1] + by };
            float2 v1 = { acc[mi][ni][2] + bx, acc[mi][ni][3] + by };
            if (relu) {
                v0.x = fmaxf(v0.x, 0.f); v0.y = fmaxf(v0.y, 0.f);
                v1.x = fmaxf(v1.x, 0.f); v1.y = fmaxf(v1.y, 0.f);
            }
            size_t i0 = (size_t)r0 * N + col;
            size_t i1 = (size_t)(r0 + 8) * N + col;
            if (Ch) {
                uint32_t h2, l2;
                sp2(v0.x, v0.y, h2, l2);
                *(uint32_t*)(Ch + i0) = h2; *(uint32_t*)(Cl + i0) = l2;
                sp2(v1.x, v1.y, h2, l2);
                *(uint32_t*)(Ch + i1) = h2; *(uint32_t*)(Cl + i1) = l2;
            } else {
                if (residual) {
                    float2 t0 = *(const float2*)(residual + i0);
                    float2 t1 = *(const float2*)(residual + i1);
                    v0.x += t0.x; v0.y += t0.y;
                    v1.x += t1.x; v1.y += t1.y;
                }
                *(float2*)(C + i0) = v0;
                *(float2*)(C + i1) = v1;
                if (part) {
                    ssum += v0.x + v0.y + v1.x + v1.y;
                    ssq  += v0.x * v0.x + v0.y * v0.y + v1.x * v1.x + v1.y * v1.y;
                }
            }
        }
    }

    if (part) {
        #pragma unroll
        for (int o = 16; o; o >>= 1) {
            ssum += __shfl_xor_sync(0xffffffffu, ssum, o);
            ssq  += __shfl_xor_sync(0xffffffffu, ssq, o);
        }
        float* rb = (float*)smg;
        if (lane == 0) { rb[wid] = ssum; rb[8 + wid] = ssq; }
        __syncthreads();
        if (tid == 0) {
            float a = 0.f, a2 = 0.f;
            #pragma unroll
            for (int w = 0; w < 8; w++) { a += rb[w]; a2 += rb[8 + w]; }
            int slot = blockIdx.x * 4 + blockIdx.y;
            part[slot * 2 + 0] = a;
            part[slot * 2 + 1] = a2;
        }
    }
}

// =================================================================
// Flash attention, tensor-core, cp.async double-buffered K/V.
// smem (ushort idx): Qh 0, Ql 9216; stage s at 18432 + s*18432:
//   Kh +0, Kl +4608, Vh +9216, Vl +13824; mask fp32 @ ushort 55296.
// Total 114688 bytes; occupancy 2 (2x114688 < 228KB/SM).
// =================================================================
#define AT3_SMEM 114688

__global__ __launch_bounds__(256, 2) void attn_mma(
    const unsigned short* __restrict__ Qh, const unsigned short* __restrict__ Ql,
    const unsigned short* __restrict__ Kh, const unsigned short* __restrict__ Kl,
    const unsigned short* __restrict__ Vh, const unsigned short* __restrict__ Vl,
    const int* __restrict__ mask,
    unsigned short* __restrict__ Oh, unsigned short* __restrict__ Ol)
{
    const int qt = blockIdx.x, h = blockIdx.y, b = blockIdx.z;
    extern __shared__ unsigned short sma[];
    const uint32_t sb = smem_u32(sma);
    float* msk = (float*)(sma + 55296);

    const int tid = threadIdx.x, wid = tid >> 5, lane = tid & 31;
    const int wm = wid * 16;
    const int lr8 = lane & 7, lmt = lane >> 3;

    // K/V chunk staging map: row 0..63, 8-col quads
    const int crow = tid >> 3, cq8 = (tid & 7) * 8;

    // ---- prologue: issue chunk 0 (stage 0) ----
    {
        #pragma unroll
        for (int it = 0; it < 2; it++) {
            int row = crow + it * 32;
            size_t g = (size_t)(b * S_ + row) * D_ + h * 64 + cq8;
            uint32_t d = 2 * (18432 + row * 72 + cq8);
            cpa16(sb + d,                Kh + g);
            cpa16(sb + d + 2 * 4608,     Kl + g);
            cpa16(sb + d + 2 * 9216,     Vh + g);
            cpa16(sb + d + 2 * 13824,    Vl + g);
        }
        cpa_commit();
    }

    // ---- Q tiles (plain copies) + mask flags ----
    #pragma unroll
    for (int it = 0; it < 4; it++) {
        int t = tid + it * 256;
        int row = t >> 3, q8 = (t & 7) * 8;
        size_t g = (size_t)(b * S_ + qt * 128 + row) * D_ + h * 64 + q8;
        *(uint4*)(sma + row * 72 + q8) = *(const uint4*)(Qh + g);
        *(uint4*)(sma + 9216 + row * 72 + q8) = *(const uint4*)(Ql + g);
        msk[t] = (mask[b * S_ + t] != 0) ? 1.0f : 0.0f;
    }

    float acc[8][4] = {};
    float m_run[2] = {-1e30f, -1e30f}, l_run[2] = {0.f, 0.f};

    for (int kc = 0; kc < 16; kc++) {
        const uint32_t cur = 18432 + (kc & 1) * 18432;
        cpa_wait0();
        __syncthreads();
        if (kc + 1 < 16) {
            const uint32_t nxt = 18432 + ((kc + 1) & 1) * 18432;
            #pragma unroll
            for (int it = 0; it < 2; it++) {
                int row = crow + it * 32;
                size_t g = (size_t)(b * S_ + (kc + 1) * 64 + row) * D_ + h * 64 + cq8;
                uint32_t d = 2 * (nxt + row * 72 + cq8);
                cpa16(sb + d,             Kh + g);
                cpa16(sb + d + 2 * 4608,  Kl + g);
                cpa16(sb + d + 2 * 9216,  Vh + g);
                cpa16(sb + d + 2 * 13824, Vl + g);
            }
            cpa_commit();
        }

        // ---- scores: S = Q K^T (3 split terms) ----
        float s[8][4] = {};
        #pragma unroll
        for (int ks = 0; ks < 4; ks++) {
            uint32_t qh4[4], ql4[4];
            uint32_t aoff = (uint32_t)(wm + (lmt & 1) * 8 + lr8) * 72
                          + ks * 16 + (lmt >> 1) * 8;
            ldsm4(qh4, sb + 2 * aoff);
            ldsm4(ql4, sb + 2 * (9216 + aoff));
            #pragma unroll
            for (int pr = 0; pr < 4; pr++) {
                uint32_t boff = (uint32_t)(pr * 16 + (lmt >> 1) * 8 + lr8) * 72
                              + ks * 16 + (lmt & 1) * 8;
                uint32_t th[4], tl[4];
                ldsm4(th, sb + 2 * (cur + boff));
                ldsm4(tl, sb + 2 * (cur + 4608 + boff));
                uint32_t bh0[2] = {th[0], th[1]}, bh1[2] = {th[2], th[3]};
                uint32_t bl0[2] = {tl[0], tl[1]}, bl1[2] = {tl[2], tl[3]};
                mma16816(s[2 * pr],     qh4, bh0);
                mma16816(s[2 * pr],     qh4, bl0);
                mma16816(s[2 * pr],     ql4, bh0);
                mma16816(s[2 * pr + 1], qh4, bh1);
                mma16816(s[2 * pr + 1], qh4, bl1);
                mma16816(s[2 * pr + 1], ql4, bh1);
            }
        }

        // ---- scale + mask ----
        #pragma unroll
        for (int nt = 0; nt < 8; nt++) {
            int colb = kc * 64 + nt * 8 + 2 * (lane & 3);
            float m0 = msk[colb], m1 = msk[colb + 1];
            s[nt][0] = (m0 != 0.f) ? s[nt][0] * 0.125f : -1e10f;
            s[nt][2] = (m0 != 0.f) ? s[nt][2] * 0.125f : -1e10f;
            s[nt][1] = (m1 != 0.f) ? s[nt][1] * 0.125f : -1e10f;
            s[nt][3] = (m1 != 0.f) ? s[nt][3] * 0.125f : -1e10f;
        }

        // ---- online softmax ----
        float mc0 = -1e30f, mc1 = -1e30f;
        #pragma unroll
        for (int nt = 0; nt < 8; nt++) {
            mc0 = fmaxf(mc0, fmaxf(s[nt][0], s[nt][1]));
            mc1 = fmaxf(mc1, fmaxf(s[nt][2], s[nt][3]));
        }
        mc0 = fmaxf(mc0, __shfl_xor_sync(0xffffffffu, mc0, 1));
        mc0 = fmaxf(mc0, __shfl_xor_sync(0xffffffffu, mc0, 2));
        mc1 = fmaxf(mc1, __shfl_xor_sync(0xffffffffu, mc1, 1));
        mc1 = fmaxf(mc1, __shfl_xor_sync(0xffffffffu, mc1, 2));
        float mn0 = fmaxf(m_run[0], mc0), mn1 = fmaxf(m_run[1], mc1);
        float sc0 = __expf(m_run[0] - mn0), sc1 = __expf(m_run[1] - mn1);
        m_run[0] = mn0; m_run[1] = mn1;
        float ls0 = 0.f, ls1 = 0.f;
        #pragma unroll
        for (int nt = 0; nt < 8; nt++) {
            s[nt][0] = __expf(s[nt][0] - mn0); ls0 += s[nt][0];
            s[nt][1] = __expf(s[nt][1] - mn0); ls0 += s[nt][1];
            s[nt][2] = __expf(s[nt][2] - mn1); ls1 += s[nt][2];
            s[nt][3] = __expf(s[nt][3] - mn1); ls1 += s[nt][3];
        }
        ls0 += __shfl_xor_sync(0xffffffffu, ls0, 1);
        ls0 += __shfl_xor_sync(0xffffffffu, ls0, 2);
        ls1 += __shfl_xor_sync(0xffffffffu, ls1, 1);
        ls1 += __shfl_xor_sync(0xffffffffu, ls1, 2);
        l_run[0] = l_run[0] * sc0 + ls0;
        l_run[1] = l_run[1] * sc1 + ls1;
        #pragma unroll
        for (int nt = 0; nt < 8; nt++) {
            acc[nt][0] *= sc0; acc[nt][1] *= sc0;
            acc[nt][2] *= sc1; acc[nt][3] *= sc1;
        }

        // ---- O += P V (3 split terms) ----
        #pragma unroll
        for (int ks = 0; ks < 4; ks++) {
            uint32_t aP[4], aL[4];
            sp2(s[2 * ks][0],     s[2 * ks][1],     aP[0], aL[0]);
            sp2(s[2 * ks][2],     s[2 * ks][3],     aP[1], aL[1]);
            sp2(s[2 * ks + 1][0], s[2 * ks + 1][1], aP[2], aL[2]);
            sp2(s[2 * ks + 1][2], s[2 * ks + 1][3], aP[3], aL[3]);
            #pragma unroll
            for (int pr = 0; pr < 4; pr++) {
                uint32_t boff = (uint32_t)(ks * 16 + (lmt & 1) * 8 + lr8) * 72
                              + pr * 16 + (lmt >> 1) * 8;
                uint32_t th[4], tl[4];
                ldsm4t(th, sb + 2 * (cur + 9216 + boff));
                ldsm4t(tl, sb + 2 * (cur + 13824 + boff));
                uint32_t bh0[2] = {th[0], th[1]}, bh1[2] = {th[2], th[3]};
                uint32_t bl0[2] = {tl[0], tl[1]}, bl1[2] = {tl[2], tl[3]};
                mma16816(acc[2 * pr],     aP, bh0);
                mma16816(acc[2 * pr],     aP, bl0);
                mma16816(acc[2 * pr],     aL, bh0);
                mma16816(acc[2 * pr + 1], aP, bh1);
                mma16816(acc[2 * pr + 1], aP, bl1);
                mma16816(acc[2 * pr + 1], aL, bh1);
            }
        }
    }

    float inv0 = 1.0f / l_run[0], inv1 = 1.0f / l_run[1];
    size_t row0 = (size_t)(b * S_ + qt * 128 + wm + (lane >> 2));
    #pragma unroll
    for (int nt = 0; nt < 8; nt++) {
        int col = h * 64 + nt * 8 + 2 * (lane & 3);
        uint32_t h2, l2;
        sp2(acc[nt][0] * inv0, acc[nt][1] * inv0, h2, l2);
        *(uint32_t*)(Oh + row0 * D_ + col) = h2;
        *(uint32_t*)(Ol + row0 * D_ + col) = l2;
        sp2(acc[nt][2] * inv1, acc[nt][3] * inv1, h2, l2);
        *(uint32_t*)(Oh + (row0 + 8) * D_ + col) = h2;
        *(uint32_t*)(Ol + (row0 + 8) * D_ + col) = l2;
    }
}

// =================================================================
// LayerNorm finalize (sums GEMM epilogue partials) + apply
// =================================================================
__global__ void ln_finalize(const float* __restrict__ part, float* __restrict__ stats)
{
    int b = threadIdx.x;
    if (b < B_) {
        float s = 0.f, s2 = 0.f;
        for (int j = 0; j < 32; j++) {
            s  += part[(b * 32 + j) * 2 + 0];
            s2 += part[(b * 32 + j) * 2 + 1];
        }
        const float inv_n = 1.0f / (float)(S_ * D_);
        float mean = s * inv_n;
        float var  = s2 * inv_n - mean * mean;
        stats[b * 2 + 0] = mean;
        stats[b * 2 + 1] = rsqrtf(var + 1e-6f);
    }
}

__global__ __launch_bounds__(256) void ln_apply(
    const float* __restrict__ X, const float* __restrict__ w,
    const float* __restrict__ bias, const float* __restrict__ stats,
    float* __restrict__ Out, unsigned short* __restrict__ hi,
    unsigned short* __restrict__ lo)
{
    int i = blockIdx.x * 256 + threadIdx.x;
    int b  = i >> 17;
    int sd = i - (b << 17);
    float mean = stats[b * 2], rstd = stats[b * 2 + 1];
    float4 xv = ((const float4*)X)[i];
    float4 wv = ((const float4*)w)[sd];
    float4 bv = ((const float4*)bias)[sd];
    float4 o;
    o.x = (xv.x - mean) * rstd * wv.x + bv.x;
    o.y = (xv.y - mean) * rstd * wv.y + bv.y;
    o.z = (xv.z - mean) * rstd * wv.z + bv.z;
    o.w = (xv.w - mean) * rstd * wv.w + bv.w;
    ((float4*)Out)[i] = o;
    if (hi) {
        ushort4 H, L;
        H.x = bfu(o.x); L.x = bfu(o.x - ubf(H.x));
        H.y = bfu(o.y); L.y = bfu(o.y - ubf(H.y));
        H.z = bfu(o.z); L.z = bfu(o.z - ubf(H.z));
        H.w = bfu(o.w); L.w = bfu(o.w - ubf(H.w));
        ((ushort4*)hi)[i] = H;
        ((ushort4*)lo)[i] = L;
    }
}

// =================================================================
extern "C" void kernel_launch(void* const* d_in, const int* in_sizes, int n_in,
                              void* d_out, int out_size)
{
    const float* x        = (const float*)d_in[0];
    const float* y        = (const float*)d_in[1];
    const int*   src_mask = (const int*)  d_in[2];
    const int*   trg_mask = (const int*)  d_in[3];
    const float* m1_wq = (const float*)d_in[4];
    const float* m1_bq = (const float*)d_in[5];
    const float* m1_wk = (const float*)d_in[6];
    const float* m1_bk = (const float*)d_in[7];
    const float* m1_wv = (const float*)d_in[8];
    const float* m1_bv = (const float*)d_in[9];
    const float* m1_wo = (const float*)d_in[10];
    const float* m1_bo = (const float*)d_in[11];
    const float* m2_wq = (const float*)d_in[12];
    const float* m2_bq = (const float*)d_in[13];
    const float* m2_wk = (const float*)d_in[14];
    const float* m2_bk = (const float*)d_in[15];
    const float* m2_wv = (const float*)d_in[16];
    const float* m2_bv = (const float*)d_in[17];
    const float* m2_wo = (const float*)d_in[18];
    const float* m2_bo = (const float*)d_in[19];
    const float* pw1   = (const float*)d_in[20];
    const float* pb1   = (const float*)d_in[21];
    const float* pw2   = (const float*)d_in[22];
    const float* pb2   = (const float*)d_in[23];
    const float* ln1_w = (const float*)d_in[24];
    const float* ln1_b = (const float*)d_in[25];
    const float* ln2_w = (const float*)d_in[26];
    const float* ln2_b = (const float*)d_in[27];
    const float* ln3_w = (const float*)d_in[28];
    const float* ln3_b = (const float*)d_in[29];
    float* out = (float*)d_out;

    float *res, *x1, *x2, *part, *stats;
    unsigned short *ah, *al, *wh, *wl;
    unsigned short *qh, *ql, *kh, *kl, *vh, *vl, *xsh, *xsl;
    cudaGetSymbolAddress((void**)&res,   g_res);
    cudaGetSymbolAddress((void**)&x1,    g_x1);
    cudaGetSymbolAddress((void**)&x2,    g_x2);
    cudaGetSymbolAddress((void**)&part,  g_part);
    cudaGetSymbolAddress((void**)&stats, g_stats);
    cudaGetSymbolAddress((void**)&ah,    g_ah);
    cudaGetSymbolAddress((void**)&al,    g_al);
    cudaGetSymbolAddress((void**)&wh,    g_wh);
    cudaGetSymbolAddress((void**)&wl,    g_wl);
    cudaGetSymbolAddress((void**)&qh,    g_qh);
    cudaGetSymbolAddress((void**)&ql,    g_ql);
    cudaGetSymbolAddress((void**)&kh,    g_kh);
    cudaGetSymbolAddress((void**)&kl,    g_kl);
    cudaGetSymbolAddress((void**)&vh,    g_vh);
    cudaGetSymbolAddress((void**)&vl,    g_vl);
    cudaGetSymbolAddress((void**)&xsh,   g_xsh);
    cudaGetSymbolAddress((void**)&xsl,   g_xsl);

    cudaFuncSetAttribute(attn_mma,
                         cudaFuncAttributeMaxDynamicSharedMemorySize, AT3_SMEM);
    cudaFuncSetAttribute(gemm_mma,
                         cudaFuncAttributeMaxDynamicSharedMemorySize, GEMM_SMEM);

    const dim3 gAttn(S_ / 128, H_, B_);
    const int  gApply = (BS_ * D_ / 4) / 256;
    const int  nActD  = BS_ * D_ / 4;
    const int  nW512  = D_ * D_ / 4;
    const int  nWff   = DFF_ * D_ / 4;
    const dim3 gG512(BS_ / 128, D_ / 128);
    const dim3 gGff1(BS_ / 128, DFF_ / 128);
    const int  cvB = 256;

    // fp32-out GEMM with residual + LN partial sums
    #define GEMMF(AH, AL, BIAS, RES, OUT, N, K, RELU, GRID) \
        gemm_mma<<<GRID, 256, GEMM_SMEM>>>(AH, AL, wh, wl, BIAS, RES, OUT, \
                                           nullptr, nullptr, part, N, K, RELU)
    // split-out GEMM
    #define GEMMS(AH, AL, BIAS, OH, OL, N, K, RELU, GRID) \
        gemm_mma<<<GRID, 256, GEMM_SMEM>>>(AH, AL, wh, wl, BIAS, nullptr, \
                                           nullptr, OH, OL, nullptr, N, K, RELU)

    // ---- self-attention ----
    cvt_split<<<(nActD + cvB - 1) / cvB, cvB>>>(x, ah, al, nActD);
    cvt_head<<<(D_ * D_) / cvB, cvB>>>(m1_wq, wh, wl);
    GEMMS(ah, al, m1_bq, qh, ql, D_, D_, 0, gG512);
    cvt_head<<<(D_ * D_) / cvB, cvB>>>(m1_wk, wh, wl);
    GEMMS(ah, al, m1_bk, kh, kl, D_, D_, 0, gG512);
    cvt_head<<<(D_ * D_) / cvB, cvB>>>(m1_wv, wh, wl);
    GEMMS(ah, al, m1_bv, vh, vl, D_, D_, 0, gG512);
    attn_mma<<<gAttn, 256, AT3_SMEM>>>(qh, ql, kh, kl, vh, vl, trg_mask, ah, al);
    cvt_split<<<(nW512 + cvB - 1) / cvB, cvB>>>(m1_wo, wh, wl, nW512);
    GEMMF(ah, al, m1_bo, x, res, D_, D_, 0, gG512);
    ln_finalize<<<1, 32>>>(part, stats);
    ln_apply<<<gApply, 256>>>(res, ln1_w, ln1_b, stats, x1, xsh, xsl);

    // ---- cross-attention ----
    cvt_head<<<(D_ * D_) / cvB, cvB>>>(m2_wq, wh, wl);
    GEMMS(xsh, xsl, m2_bq, qh, ql, D_, D_, 0, gG512);
    cvt_split<<<(nActD + cvB - 1) / cvB, cvB>>>(y, ah, al, nActD);
    cvt_head<<<(D_ * D_) / cvB, cvB>>>(m2_wk, wh, wl);
    GEMMS(ah, al, m2_bk, kh, kl, D_, D_, 0, gG512);
    cvt_head<<<(D_ * D_) / cvB, cvB>>>(m2_wv, wh, wl);
    GEMMS(ah, al, m2_bv, vh, vl, D_, D_, 0, gG512);
    attn_mma<<<gAttn, 256, AT3_SMEM>>>(qh, ql, kh, kl, vh, vl, src_mask, ah, al);
    cvt_split<<<(nW512 + cvB - 1) / cvB, cvB>>>(m2_wo, wh, wl, nW512);
    GEMMF(ah, al, m2_bo, x1, res, D_, D_, 0, gG512);
    ln_finalize<<<1, 32>>>(part, stats);
    ln_apply<<<gApply, 256>>>(res, ln2_w, ln2_b, stats, x2, xsh, xsl);

    // ---- FFN ----
    cvt_split<<<(nWff + cvB - 1) / cvB, cvB>>>(pw1, wh, wl, nWff);
    GEMMS(xsh, xsl, pb1, ah, al, DFF_, D_, 1, gGff1);
    cvt_split<<<(nWff + cvB - 1) / cvB, cvB>>>(pw2, wh, wl, nWff);
    GEMMF(ah, al, pb2, x2, res, D_, DFF_, 0, gG512);
    ln_finalize<<<1, 32>>>(part, stats);
    ln_apply<<<gApply, 256>>>(res, ln3_w, ln3_b, stats, out, nullptr, nullptr);

    #undef GEMMF
    #undef GEMMS
}